// round 4
// baseline (speedup 1.0000x reference)
#include <cuda_runtime.h>
#include <cstdint>

// Problem constants (B derived at launch; S, D fixed per the dataset)
#define S_LEN   200
#define D_DIM   64
#define TPB     256
#define XS      65            // padded smem row stride for Xu (bank-conflict-free)

// shared memory layout (in floats)
#define OFF_XU   0                       // 200*65 = 13000
#define OFF_M    (OFF_XU + S_LEN*XS)     // 4096
#define OFF_C0   (OFF_M  + 64*64)        // 64
#define OFF_W2   (OFF_C0 + 64)           // 2048
#define OFF_W3   (OFF_W2 + 64*32)        // 32
#define OFF_Q    (OFF_W3 + 32)           // 64
#define OFF_B2   (OFF_Q  + 64)           // 32
#define OFF_LG   (OFF_B2 + 32)           // 208 (200 used, padded)
#define OFF_RED  (OFF_LG + 208)          // 40
#define OFF_POOL (OFF_RED + 40)          // 64
#define SMEM_FLOATS (OFF_POOL + 64)
#define SMEM_BYTES  (SMEM_FLOATS * 4)

typedef unsigned long long u64;

__device__ __forceinline__ u64 pack2(float lo, float hi) {
    u64 r;
    asm("mov.b64 %0, {%1, %2};" : "=l"(r) : "f"(lo), "f"(hi));
    return r;
}
__device__ __forceinline__ void unpack2(u64 v, float& lo, float& hi) {
    asm("mov.b64 {%0, %1}, %2;" : "=f"(lo), "=f"(hi) : "l"(v));
}
__device__ __forceinline__ void fma2(u64& acc, u64 a, u64 b) {
    asm("fma.rn.f32x2 %0, %1, %2, %0;" : "+l"(acc) : "l"(a), "l"(b));
}

__global__ void __launch_bounds__(TPB, 1)
din_user_repr_kernel(const float* __restrict__ em,
                     const float* __restrict__ eu,
                     const float* __restrict__ Xu,
                     const float* __restrict__ W1,
                     const float* __restrict__ b1,
                     const float* __restrict__ W2,
                     const float* __restrict__ b2,
                     const float* __restrict__ W3,
                     const float* __restrict__ b3,
                     const float* __restrict__ gamma,
                     const float* __restrict__ beta,
                     const float* __restrict__ mmean,
                     const float* __restrict__ mvar,
                     float* __restrict__ out)
{
    extern __shared__ float sm[];
    float* sXu  = sm + OFF_XU;
    float* sM   = sm + OFF_M;
    float* sC0  = sm + OFF_C0;
    float* sW2  = sm + OFF_W2;
    float* sW3  = sm + OFF_W3;
    float* sQ   = sm + OFF_Q;
    float* sB2  = sm + OFF_B2;
    float* sLg  = sm + OFF_LG;
    float* sRed = sm + OFF_RED;
    float* sPool= sm + OFF_POOL;

    const int b = blockIdx.x;
    const int t = threadIdx.x;

    // ---- stage 0: loads --------------------------------------------------
    if (t < 64)  sQ[t]  = em[(size_t)b * 64 + t];
    if (t >= 64 && t < 96) sB2[t - 64] = b2[t - 64];
    if (t >= 96 && t < 128) sW3[t - 96] = W3[t - 96];
    for (int i = t; i < 64 * 32; i += TPB) sW2[i] = W2[i];

    // Xu tile: coalesced float4 global reads, scattered into stride-65 smem
    {
        const float4* Xg = (const float4*)(Xu + (size_t)b * S_LEN * D_DIM);
        for (int i = t; i < S_LEN * D_DIM / 4; i += TPB) {
            float4 v = Xg[i];
            int e = i * 4;
            int row = e >> 6, col = e & 63;
            float* dst = sXu + row * XS + col;
            dst[0] = v.x; dst[1] = v.y; dst[2] = v.z; dst[3] = v.w;
        }
    }
    __syncthreads();

    // ---- stage 1: per-row folded weights ----------------------------------
    // M[d][j] = W1[64+d][j] - W1[128+d][j] + q[d]*W1[192+d][j]
    for (int i = t; i < 64 * 64; i += TPB) {
        int d = i >> 6, j = i & 63;
        sM[i] = W1[(64 + d) * 64 + j] - W1[(128 + d) * 64 + j]
              + sQ[d] * W1[(192 + d) * 64 + j];
    }
    // c0[j] = b1[j] + sum_d q[d]*(W1[d][j] + W1[128+d][j])
    if (t < 64) {
        float acc = b1[t];
        #pragma unroll 4
        for (int d = 0; d < 64; d++)
            acc += sQ[d] * (W1[d * 64 + t] + W1[(128 + d) * 64 + t]);
        sC0[t] = acc;
    }
    __syncthreads();

    // ---- stage 2: per-position MLP (packed f32x2 FMA) ---------------------
    if (t < S_LEN) {
        u64 h1p[32];
        const u64* c0p = (const u64*)sC0;
        #pragma unroll
        for (int j = 0; j < 32; j++) h1p[j] = c0p[j];

        const float* xrow = sXu + t * XS;
        const u64* Mb = (const u64*)sM;
        #pragma unroll 2
        for (int d = 0; d < 64; d++) {
            float xd = xrow[d];
            u64 xx = pack2(xd, xd);
            const u64* mrow = Mb + d * 32;
            #pragma unroll
            for (int j = 0; j < 32; j++) fma2(h1p[j], xx, mrow[j]);
        }

        u64 h2p[16];
        const u64* b2p = (const u64*)sB2;
        #pragma unroll
        for (int k = 0; k < 16; k++) h2p[k] = b2p[k];

        const u64* W2p = (const u64*)sW2;
        #pragma unroll 2
        for (int jj = 0; jj < 32; jj++) {
            float lo, hi;
            unpack2(h1p[jj], lo, hi);
            lo = fmaxf(lo, 0.0f);
            hi = fmaxf(hi, 0.0f);
            u64 rlo = pack2(lo, lo);
            u64 rhi = pack2(hi, hi);
            const u64* wa = W2p + (2 * jj) * 16;
            const u64* wb = W2p + (2 * jj + 1) * 16;
            #pragma unroll
            for (int k = 0; k < 16; k++) {
                fma2(h2p[k], rlo, wa[k]);
                fma2(h2p[k], rhi, wb[k]);
            }
        }

        float lg = b3[0];
        #pragma unroll
        for (int k = 0; k < 16; k++) {
            float lo, hi;
            unpack2(h2p[k], lo, hi);
            lg += fmaxf(lo, 0.0f) * sW3[2 * k] + fmaxf(hi, 0.0f) * sW3[2 * k + 1];
        }
        sLg[t] = lg;
    }
    __syncthreads();

    // ---- stage 3: softmax over S ------------------------------------------
    const float NEG_INF = __int_as_float(0xff800000);
    float mx = NEG_INF;
    for (int i = t; i < S_LEN; i += TPB) mx = fmaxf(mx, sLg[i]);
    #pragma unroll
    for (int o = 16; o > 0; o >>= 1) mx = fmaxf(mx, __shfl_xor_sync(0xffffffffu, mx, o));
    if ((t & 31) == 0) sRed[t >> 5] = mx;
    __syncthreads();
    if (t == 0) {
        float m = sRed[0];
        #pragma unroll
        for (int w = 1; w < TPB / 32; w++) m = fmaxf(m, sRed[w]);
        sRed[32] = m;
    }
    __syncthreads();
    mx = sRed[32];

    float se = 0.0f;
    for (int i = t; i < S_LEN; i += TPB) {
        float v = expf(sLg[i] - mx);
        sLg[i] = v;
        se += v;
    }
    #pragma unroll
    for (int o = 16; o > 0; o >>= 1) se += __shfl_xor_sync(0xffffffffu, se, o);
    if ((t & 31) == 0) sRed[t >> 5] = se;
    __syncthreads();
    if (t == 0) {
        float s = 0.0f;
        #pragma unroll
        for (int w = 0; w < TPB / 32; w++) s += sRed[w];
        sRed[33] = 1.0f / s;
    }
    __syncthreads();
    const float invSum = sRed[33];

    // ---- stage 4: weighted pool (bank-conflict-free via XS pad) ------------
    if (t < 64) {
        float acc = 0.0f;
        #pragma unroll 4
        for (int s = 0; s < S_LEN; s++)
            acc += sLg[s] * sXu[s * XS + t];
        sPool[t] = acc * invSum;
    }
    __syncthreads();

    // ---- stage 5: BN + concat epilogue -------------------------------------
    float* ob = out + (size_t)b * 192;
    if (t < 128) {
        float v = (t < 64) ? sPool[t] : sQ[t - 64];
        ob[t] = (v - mmean[t]) * rsqrtf(mvar[t] + 1e-3f) * gamma[t] + beta[t];
    } else if (t < 192) {
        ob[t] = eu[(size_t)b * 64 + (t - 128)];
    }
}

extern "C" void kernel_launch(void* const* d_in, const int* in_sizes, int n_in,
                              void* d_out, int out_size)
{
    const float* em    = (const float*)d_in[0];
    const float* eu    = (const float*)d_in[1];
    const float* Xu    = (const float*)d_in[2];
    const float* W1    = (const float*)d_in[3];
    const float* b1    = (const float*)d_in[4];
    const float* W2    = (const float*)d_in[5];
    const float* b2    = (const float*)d_in[6];
    const float* W3    = (const float*)d_in[7];
    const float* b3    = (const float*)d_in[8];
    const float* gamma = (const float*)d_in[9];
    const float* beta  = (const float*)d_in[10];
    const float* mmean = (const float*)d_in[11];
    const float* mvar  = (const float*)d_in[12];
    float* out = (float*)d_out;

    const int B = in_sizes[0] / D_DIM;

    cudaFuncSetAttribute(din_user_repr_kernel,
                         cudaFuncAttributeMaxDynamicSharedMemorySize, SMEM_BYTES);
    din_user_repr_kernel<<<B, TPB, SMEM_BYTES>>>(
        em, eu, Xu, W1, b1, W2, b2, W3, b3, gamma, beta, mmean, mvar, out);
}

// round 6
// speedup vs baseline: 1.9357x; 1.9357x over previous
#include <cuda_runtime.h>
#include <cstdint>

#define S_LEN   200
#define D_DIM   64
#define TPB     128
#define XS      65            // padded smem row stride for Xu (bank-conflict-free)

// shared memory layout (in floats); 16B alignment holds for XU/M/C0/W2
#define OFF_XU    0                        // 200*65 = 13000  (52000 B, %16==0)
#define OFF_M     (OFF_XU + S_LEN*XS)      // 4096
#define OFF_C0    (OFF_M  + 64*64)         // 64
#define OFF_W2    (OFF_C0 + 64)            // 2048
#define OFF_W3    (OFF_W2 + 64*32)         // 32
#define OFF_Q     (OFF_W3 + 32)            // 64
#define OFF_B2    (OFF_Q  + 64)            // 32
#define OFF_LG    (OFF_B2 + 32)            // 208 (200 used)
#define OFF_RED   (OFF_LG + 208)           // 40
#define OFF_POOL2 (OFF_RED + 40)           // 128 (2 groups x 64)
#define SMEM_FLOATS (OFF_POOL2 + 128)
#define SMEM_BYTES  (SMEM_FLOATS * 4)

typedef unsigned long long u64;

__device__ __forceinline__ u64 pack2(float lo, float hi) {
    u64 r;
    asm("mov.b64 %0, {%1, %2};" : "=l"(r) : "f"(lo), "f"(hi));
    return r;
}
__device__ __forceinline__ void unpack2(u64 v, float& lo, float& hi) {
    asm("mov.b64 {%0, %1}, %2;" : "=f"(lo), "=f"(hi) : "l"(v));
}
__device__ __forceinline__ void fma2(u64& acc, u64 a, u64 b) {
    asm("fma.rn.f32x2 %0, %1, %2, %0;" : "+l"(acc) : "l"(a), "l"(b));
}

__global__ void __launch_bounds__(TPB, 2)
din_user_repr_kernel(const float* __restrict__ em,
                     const float* __restrict__ eu,
                     const float* __restrict__ Xu,
                     const float* __restrict__ W1,
                     const float* __restrict__ b1,
                     const float* __restrict__ W2,
                     const float* __restrict__ b2,
                     const float* __restrict__ W3,
                     const float* __restrict__ b3,
                     const float* __restrict__ gamma,
                     const float* __restrict__ beta,
                     const float* __restrict__ mmean,
                     const float* __restrict__ mvar,
                     float* __restrict__ out)
{
    extern __shared__ float sm[];
    float* sXu   = sm + OFF_XU;
    float* sM    = sm + OFF_M;
    float* sC0   = sm + OFF_C0;
    float* sW2   = sm + OFF_W2;
    float* sW3   = sm + OFF_W3;
    float* sQ    = sm + OFF_Q;
    float* sB2   = sm + OFF_B2;
    float* sLg   = sm + OFF_LG;
    float* sRed  = sm + OFF_RED;
    float* sPool2= sm + OFF_POOL2;

    const int b = blockIdx.x;
    const int t = threadIdx.x;

    // ---- stage 0: loads ----------------------------------------------------
    if (t < 64)       sQ[t]       = em[(size_t)b * 64 + t];
    else if (t < 96)  sB2[t - 64] = b2[t - 64];
    else              sW3[t - 96] = W3[t - 96];
    for (int i = t; i < 64 * 32; i += TPB) sW2[i] = W2[i];

    {   // Xu tile: coalesced float4 reads, scattered into stride-65 smem
        const float4* Xg = (const float4*)(Xu + (size_t)b * S_LEN * D_DIM);
        for (int i = t; i < S_LEN * D_DIM / 4; i += TPB) {
            float4 v = Xg[i];
            int e = i * 4;
            int row = e >> 6, col = e & 63;
            float* dst = sXu + row * XS + col;
            dst[0] = v.x; dst[1] = v.y; dst[2] = v.z; dst[3] = v.w;
        }
    }
    __syncthreads();

    // ---- stage 1: per-row folded weights ------------------------------------
    // M[d][j] = W1[64+d][j] - W1[128+d][j] + q[d]*W1[192+d][j]
    for (int i = t; i < 64 * 64; i += TPB) {
        int d = i >> 6, j = i & 63;
        sM[i] = W1[(64 + d) * 64 + j] - W1[(128 + d) * 64 + j]
              + sQ[d] * W1[(192 + d) * 64 + j];
    }
    // c0[j] = b1[j] + sum_d q[d]*(W1[d][j] + W1[128+d][j])
    if (t < 64) {
        float acc = b1[t];
        #pragma unroll 4
        for (int d = 0; d < 64; d++)
            acc += sQ[d] * (W1[d * 64 + t] + W1[(128 + d) * 64 + t]);
        sC0[t] = acc;
    }
    __syncthreads();

    // ---- stage 2: MLP, 2 positions per thread (t and t+100) -----------------
    if (t < 100) {
        u64 h2a[16], h2b[16];
        {
            const u64* b2p = (const u64*)sB2;
            #pragma unroll
            for (int k = 0; k < 16; k++) { u64 v = b2p[k]; h2a[k] = v; h2b[k] = v; }
        }

        const float* x0 = sXu + t * XS;
        const float* x1 = sXu + (t + 100) * XS;
        const u64*   Mb = (const u64*)sM;
        const u64*   W2p = (const u64*)sW2;

        for (int h = 0; h < 2; h++) {          // j-halves [32h, 32h+32)
            // ---- layer 1 half: h1[32h..32h+31] for both positions ----
            u64 h1a[16], h1b[16];
            {
                const ulonglong2* c0v = (const ulonglong2*)((const u64*)sC0 + h * 16);
                #pragma unroll
                for (int k = 0; k < 8; k++) {
                    ulonglong2 c = c0v[k];
                    h1a[2*k] = c.x; h1a[2*k+1] = c.y;
                    h1b[2*k] = c.x; h1b[2*k+1] = c.y;
                }
            }
            const u64* mbase = Mb + h * 16;
            #pragma unroll 4
            for (int d = 0; d < 64; d++) {
                float va = x0[d], vb = x1[d];
                u64 xa = pack2(va, va);
                u64 xb = pack2(vb, vb);
                const ulonglong2* mv = (const ulonglong2*)(mbase + d * 32);
                #pragma unroll
                for (int k = 0; k < 8; k++) {
                    ulonglong2 m = mv[k];
                    fma2(h1a[2*k],   xa, m.x); fma2(h1a[2*k+1], xa, m.y);
                    fma2(h1b[2*k],   xb, m.x); fma2(h1b[2*k+1], xb, m.y);
                }
            }

            // ---- layer 2 partial: accumulate relu(h1 half) @ W2 ----
            const u64* w2base = W2p + h * 32 * 16;   // rows 32h..32h+31
            #pragma unroll
            for (int kk = 0; kk < 16; kk++) {
                float la, ha, lb, hb;
                unpack2(h1a[kk], la, ha);
                unpack2(h1b[kk], lb, hb);
                la = fmaxf(la, 0.0f); ha = fmaxf(ha, 0.0f);
                lb = fmaxf(lb, 0.0f); hb = fmaxf(hb, 0.0f);
                u64 ral = pack2(la, la), rah = pack2(ha, ha);
                u64 rbl = pack2(lb, lb), rbh = pack2(hb, hb);
                const ulonglong2* wav = (const ulonglong2*)(w2base + (2*kk)     * 16);
                const ulonglong2* wbv = (const ulonglong2*)(w2base + (2*kk + 1) * 16);
                #pragma unroll
                for (int k = 0; k < 8; k++) {
                    ulonglong2 wa = wav[k];
                    ulonglong2 wb = wbv[k];
                    fma2(h2a[2*k],   ral, wa.x); fma2(h2a[2*k+1], ral, wa.y);
                    fma2(h2a[2*k],   rah, wb.x); fma2(h2a[2*k+1], rah, wb.y);
                    fma2(h2b[2*k],   rbl, wa.x); fma2(h2b[2*k+1], rbl, wa.y);
                    fma2(h2b[2*k],   rbh, wb.x); fma2(h2b[2*k+1], rbh, wb.y);
                }
            }
        }

        // ---- layer 3: logits ----
        float bb3 = __ldg(b3);
        float lga = bb3, lgb = bb3;
        #pragma unroll
        for (int k = 0; k < 16; k++) {
            float lo, hi;
            unpack2(h2a[k], lo, hi);
            lga += fmaxf(lo, 0.0f) * sW3[2*k] + fmaxf(hi, 0.0f) * sW3[2*k + 1];
            unpack2(h2b[k], lo, hi);
            lgb += fmaxf(lo, 0.0f) * sW3[2*k] + fmaxf(hi, 0.0f) * sW3[2*k + 1];
        }
        sLg[t]       = lga;
        sLg[t + 100] = lgb;
    }
    __syncthreads();

    // ---- stage 3: softmax over S --------------------------------------------
    const float NEG_INF = __int_as_float(0xff800000);
    float mx = NEG_INF;
    for (int i = t; i < S_LEN; i += TPB) mx = fmaxf(mx, sLg[i]);
    #pragma unroll
    for (int o = 16; o > 0; o >>= 1) mx = fmaxf(mx, __shfl_xor_sync(0xffffffffu, mx, o));
    if ((t & 31) == 0) sRed[t >> 5] = mx;
    __syncthreads();
    if (t == 0) {
        float m = sRed[0];
        #pragma unroll
        for (int w = 1; w < TPB / 32; w++) m = fmaxf(m, sRed[w]);
        sRed[32] = m;
    }
    __syncthreads();
    mx = sRed[32];

    float se = 0.0f;
    for (int i = t; i < S_LEN; i += TPB) {
        float v = expf(sLg[i] - mx);
        sLg[i] = v;
        se += v;
    }
    #pragma unroll
    for (int o = 16; o > 0; o >>= 1) se += __shfl_xor_sync(0xffffffffu, se, o);
    if ((t & 31) == 0) sRed[t >> 5] = se;
    __syncthreads();
    if (t == 0) {
        float s = 0.0f;
        #pragma unroll
        for (int w = 0; w < TPB / 32; w++) s += sRed[w];
        sRed[33] = 1.0f / s;
    }
    __syncthreads();
    const float invSum = sRed[33];

    // ---- stage 4: weighted pool, all 128 threads (2 s-groups x 64 d) ---------
    {
        const int g = t >> 6;           // 0 or 1
        const int d = t & 63;
        const int s0 = g * 100;
        float acc = 0.0f;
        #pragma unroll 4
        for (int s = s0; s < s0 + 100; s++)
            acc += sLg[s] * sXu[s * XS + d];
        sPool2[t] = acc;
    }
    __syncthreads();

    // ---- stage 5: BN + concat epilogue ---------------------------------------
    float* ob = out + (size_t)b * 192;
    for (int i = t; i < 192; i += TPB) {
        if (i < 128) {
            float v = (i < 64) ? (sPool2[i] + sPool2[64 + i]) * invSum
                               : sQ[i - 64];
            ob[i] = (v - mmean[i]) * rsqrtf(mvar[i] + 1e-3f) * gamma[i] + beta[i];
        } else {
            ob[i] = eu[(size_t)b * 64 + (i - 128)];
        }
    }
}

extern "C" void kernel_launch(void* const* d_in, const int* in_sizes, int n_in,
                              void* d_out, int out_size)
{
    const float* em    = (const float*)d_in[0];
    const float* eu    = (const float*)d_in[1];
    const float* Xu    = (const float*)d_in[2];
    const float* W1    = (const float*)d_in[3];
    const float* b1    = (const float*)d_in[4];
    const float* W2    = (const float*)d_in[5];
    const float* b2    = (const float*)d_in[6];
    const float* W3    = (const float*)d_in[7];
    const float* b3    = (const float*)d_in[8];
    const float* gamma = (const float*)d_in[9];
    const float* beta  = (const float*)d_in[10];
    const float* mmean = (const float*)d_in[11];
    const float* mvar  = (const float*)d_in[12];
    float* out = (float*)d_out;

    const int B = in_sizes[0] / D_DIM;

    cudaFuncSetAttribute(din_user_repr_kernel,
                         cudaFuncAttributeMaxDynamicSharedMemorySize, SMEM_BYTES);
    din_user_repr_kernel<<<B, TPB, SMEM_BYTES>>>(
        em, eu, Xu, W1, b1, W2, b2, W3, b3, gamma, beta, mmean, mvar, out);
}

// round 8
// speedup vs baseline: 1.9869x; 1.0264x over previous
#include <cuda_runtime.h>
#include <cstdint>

#define S_LEN   200
#define D_DIM   64
#define TPB     128

// shared memory layout (floats). Xu stored at stride 64 with XOR-quad swizzle:
// physical quad index = qd ^ (row & 7)  (qd = d>>2). 16B aligned everywhere.
#define OFF_XU    0                        // 200*64 = 12800
#define OFF_M     (OFF_XU + S_LEN*64)      // 4096
#define OFF_C0    (OFF_M  + 64*64)         // 64
#define OFF_Q     (OFF_C0 + 64)            // 64
#define OFF_LG    (OFF_Q  + 64)            // 208 (200 used)
#define OFF_RED   (OFF_LG + 208)           // 40
#define OFF_POOL2 (OFF_RED + 40)           // 128 (2 groups x 64)
#define SMEM_FLOATS (OFF_POOL2 + 128)      // 17400
#define SMEM_BYTES  (SMEM_FLOATS * 4)      // 69600 B -> 3 CTAs/SM

typedef unsigned long long u64;

__device__ __forceinline__ u64 pack2(float lo, float hi) {
    u64 r;
    asm("mov.b64 %0, {%1, %2};" : "=l"(r) : "f"(lo), "f"(hi));
    return r;
}
__device__ __forceinline__ void unpack2(u64 v, float& lo, float& hi) {
    asm("mov.b64 {%0, %1}, %2;" : "=f"(lo), "=f"(hi) : "l"(v));
}
__device__ __forceinline__ void fma2(u64& acc, u64 a, u64 b) {
    asm("fma.rn.f32x2 %0, %1, %2, %0;" : "+l"(acc) : "l"(a), "l"(b));
}

__global__ void __launch_bounds__(TPB, 3)
din_user_repr_kernel(const float* __restrict__ em,
                     const float* __restrict__ eu,
                     const float* __restrict__ Xu,
                     const float* __restrict__ W1,
                     const float* __restrict__ b1,
                     const float* __restrict__ W2,
                     const float* __restrict__ b2,
                     const float* __restrict__ W3,
                     const float* __restrict__ b3,
                     const float* __restrict__ gamma,
                     const float* __restrict__ beta,
                     const float* __restrict__ mmean,
                     const float* __restrict__ mvar,
                     float* __restrict__ out)
{
    extern __shared__ float sm[];
    float* sXu   = sm + OFF_XU;
    float* sM    = sm + OFF_M;
    float* sC0   = sm + OFF_C0;
    float* sQ    = sm + OFF_Q;
    float* sLg   = sm + OFF_LG;
    float* sRed  = sm + OFF_RED;
    float* sPool2= sm + OFF_POOL2;

    const int b = blockIdx.x;
    const int t = threadIdx.x;

    // ---- stage 0: loads ----------------------------------------------------
    if (t < 64) sQ[t] = em[(size_t)b * 64 + t];

    {   // Xu tile: coalesced float4 reads -> swizzled smem (stride 64, quad XOR)
        const float4* Xg = (const float4*)(Xu + (size_t)b * S_LEN * D_DIM);
        for (int i = t; i < S_LEN * D_DIM / 4; i += TPB) {
            float4 v = Xg[i];
            int e   = i * 4;
            int row = e >> 6;
            int qd  = (e >> 2) & 15;
            int pq  = qd ^ (row & 7);
            *(float4*)(sXu + row * 64 + pq * 4) = v;
        }
    }
    __syncthreads();

    // ---- stage 1: per-row folded weights ------------------------------------
    // M[d][j] = W1[64+d][j] - W1[128+d][j] + q[d]*W1[192+d][j]
    for (int i = t; i < 64 * 64; i += TPB) {
        int d = i >> 6, j = i & 63;
        sM[i] = W1[(64 + d) * 64 + j] - W1[(128 + d) * 64 + j]
              + sQ[d] * W1[(192 + d) * 64 + j];
    }
    // c0[j] = b1[j] + sum_d q[d]*(W1[d][j] + W1[128+d][j])
    if (t < 64) {
        float acc = b1[t];
        #pragma unroll 4
        for (int d = 0; d < 64; d++)
            acc += sQ[d] * (W1[d * 64 + t] + W1[(128 + d) * 64 + t]);
        sC0[t] = acc;
    }
    __syncthreads();

    // ---- stage 2: MLP, 2 positions per thread (t and t+100) -----------------
    if (t < 100) {
        u64 h2a[16], h2b[16];
        {   // init from b2 (global, broadcast LDG, L1-resident)
            const float4* b2v = (const float4*)b2;
            #pragma unroll
            for (int k = 0; k < 8; k++) {
                float4 v = __ldg(b2v + k);
                u64 p0 = pack2(v.x, v.y), p1 = pack2(v.z, v.w);
                h2a[2*k] = p0; h2a[2*k+1] = p1;
                h2b[2*k] = p0; h2b[2*k+1] = p1;
            }
        }

        const int r0 = t, r1 = t + 100;
        const float* x0b = sXu + r0 * 64;
        const float* x1b = sXu + r1 * 64;
        const int sw0 = (r0 & 7) << 2;   // byte-quad swizzle (in floats: *4)
        const int sw1 = (r1 & 7) << 2;
        const u64* Mb = (const u64*)sM;

        for (int h = 0; h < 2; h++) {          // j-halves [32h, 32h+32)
            // ---- layer 1 half: h1[32h..32h+31] for both positions ----
            u64 h1a[16], h1b[16];
            {
                const ulonglong2* c0v = (const ulonglong2*)((const u64*)sC0 + h * 16);
                #pragma unroll
                for (int k = 0; k < 8; k++) {
                    ulonglong2 c = c0v[k];
                    h1a[2*k] = c.x; h1a[2*k+1] = c.y;
                    h1b[2*k] = c.x; h1b[2*k+1] = c.y;
                }
            }
            const u64* mbase = Mb + h * 16;
            #pragma unroll 2
            for (int q = 0; q < 16; q++) {     // quads of d
                // swizzled, 16B-aligned, conflict-free row loads
                float4 va = *(const float4*)(x0b + (((q << 2) ^ sw0)));
                float4 vb = *(const float4*)(x1b + (((q << 2) ^ sw1)));
                const float fa[4] = {va.x, va.y, va.z, va.w};
                const float fb[4] = {vb.x, vb.y, vb.z, vb.w};
                #pragma unroll
                for (int dd = 0; dd < 4; dd++) {
                    u64 xa = pack2(fa[dd], fa[dd]);
                    u64 xb = pack2(fb[dd], fb[dd]);
                    const ulonglong2* mv = (const ulonglong2*)(mbase + (q * 4 + dd) * 32);
                    #pragma unroll
                    for (int k = 0; k < 8; k++) {
                        ulonglong2 m = mv[k];
                        fma2(h1a[2*k],   xa, m.x); fma2(h1a[2*k+1], xa, m.y);
                        fma2(h1b[2*k],   xb, m.x); fma2(h1b[2*k+1], xb, m.y);
                    }
                }
            }

            // ---- layer 2 partial: relu(h1 half) @ W2 rows [32h..32h+31] ----
            // W2 read straight from global (broadcast LDG.128, L1-resident)
            const float4* w2g = (const float4*)(W2 + (h * 32) * 32);
            #pragma unroll
            for (int kk = 0; kk < 16; kk++) {
                float la, ha, lb, hb;
                unpack2(h1a[kk], la, ha);
                unpack2(h1b[kk], lb, hb);
                la = fmaxf(la, 0.0f); ha = fmaxf(ha, 0.0f);
                lb = fmaxf(lb, 0.0f); hb = fmaxf(hb, 0.0f);
                u64 ral = pack2(la, la), rah = pack2(ha, ha);
                u64 rbl = pack2(lb, lb), rbh = pack2(hb, hb);
                const float4* wa = w2g + (2 * kk)     * 8;  // row 32h+2kk
                const float4* wb = w2g + (2 * kk + 1) * 8;  // row 32h+2kk+1
                #pragma unroll
                for (int k = 0; k < 8; k++) {
                    float4 a4 = __ldg(wa + k);
                    float4 b4 = __ldg(wb + k);
                    u64 wax = pack2(a4.x, a4.y), way = pack2(a4.z, a4.w);
                    u64 wbx = pack2(b4.x, b4.y), wby = pack2(b4.z, b4.w);
                    fma2(h2a[2*k],   ral, wax); fma2(h2a[2*k+1], ral, way);
                    fma2(h2a[2*k],   rah, wbx); fma2(h2a[2*k+1], rah, wby);
                    fma2(h2b[2*k],   rbl, wax); fma2(h2b[2*k+1], rbl, way);
                    fma2(h2b[2*k],   rbh, wbx); fma2(h2b[2*k+1], rbh, wby);
                }
            }
        }

        // ---- layer 3: logits (W3/b3 via broadcast LDG) ----
        float bb3 = __ldg(b3);
        float lga = bb3, lgb = bb3;
        #pragma unroll
        for (int k = 0; k < 16; k++) {
            float w0 = __ldg(W3 + 2 * k);
            float w1 = __ldg(W3 + 2 * k + 1);
            float lo, hi;
            unpack2(h2a[k], lo, hi);
            lga += fmaxf(lo, 0.0f) * w0 + fmaxf(hi, 0.0f) * w1;
            unpack2(h2b[k], lo, hi);
            lgb += fmaxf(lo, 0.0f) * w0 + fmaxf(hi, 0.0f) * w1;
        }
        sLg[t]       = lga;
        sLg[t + 100] = lgb;
    }
    __syncthreads();

    // ---- stage 3: softmax over S --------------------------------------------
    const float NEG_INF = __int_as_float(0xff800000);
    float mx = NEG_INF;
    for (int i = t; i < S_LEN; i += TPB) mx = fmaxf(mx, sLg[i]);
    #pragma unroll
    for (int o = 16; o > 0; o >>= 1) mx = fmaxf(mx, __shfl_xor_sync(0xffffffffu, mx, o));
    if ((t & 31) == 0) sRed[t >> 5] = mx;
    __syncthreads();
    if (t == 0) {
        float m = sRed[0];
        #pragma unroll
        for (int w = 1; w < TPB / 32; w++) m = fmaxf(m, sRed[w]);
        sRed[32] = m;
    }
    __syncthreads();
    mx = sRed[32];

    float se = 0.0f;
    for (int i = t; i < S_LEN; i += TPB) {
        float v = expf(sLg[i] - mx);
        sLg[i] = v;
        se += v;
    }
    #pragma unroll
    for (int o = 16; o > 0; o >>= 1) se += __shfl_xor_sync(0xffffffffu, se, o);
    if ((t & 31) == 0) sRed[t >> 5] = se;
    __syncthreads();
    if (t == 0) {
        float s = 0.0f;
        #pragma unroll
        for (int w = 0; w < TPB / 32; w++) s += sRed[w];
        sRed[33] = 1.0f / s;
    }
    __syncthreads();
    const float invSum = sRed[33];

    // ---- stage 4: weighted pool (swizzled column reads, conflict-free) -------
    {
        const int g  = t >> 6;          // 0 or 1
        const int d  = t & 63;
        const int qd = d >> 2, dl = d & 3;
        const int s0 = g * 100;
        float acc = 0.0f;
        #pragma unroll 4
        for (int s = s0; s < s0 + 100; s++) {
            int pq = qd ^ (s & 7);
            acc += sLg[s] * sXu[s * 64 + pq * 4 + dl];
        }
        sPool2[t] = acc;
    }
    __syncthreads();

    // ---- stage 5: BN + concat epilogue ---------------------------------------
    float* ob = out + (size_t)b * 192;
    for (int i = t; i < 192; i += TPB) {
        if (i < 128) {
            float v = (i < 64) ? (sPool2[i] + sPool2[64 + i]) * invSum
                               : sQ[i - 64];
            ob[i] = (v - mmean[i]) * rsqrtf(mvar[i] + 1e-3f) * gamma[i] + beta[i];
        } else {
            ob[i] = eu[(size_t)b * 64 + (i - 128)];
        }
    }
}

extern "C" void kernel_launch(void* const* d_in, const int* in_sizes, int n_in,
                              void* d_out, int out_size)
{
    const float* em    = (const float*)d_in[0];
    const float* eu    = (const float*)d_in[1];
    const float* Xu    = (const float*)d_in[2];
    const float* W1    = (const float*)d_in[3];
    const float* b1    = (const float*)d_in[4];
    const float* W2    = (const float*)d_in[5];
    const float* b2    = (const float*)d_in[6];
    const float* W3    = (const float*)d_in[7];
    const float* b3    = (const float*)d_in[8];
    const float* gamma = (const float*)d_in[9];
    const float* beta  = (const float*)d_in[10];
    const float* mmean = (const float*)d_in[11];
    const float* mvar  = (const float*)d_in[12];
    float* out = (float*)d_out;

    const int B = in_sizes[0] / D_DIM;

    cudaFuncSetAttribute(din_user_repr_kernel,
                         cudaFuncAttributeMaxDynamicSharedMemorySize, SMEM_BYTES);
    din_user_repr_kernel<<<B, TPB, SMEM_BYTES>>>(
        em, eu, Xu, W1, b1, W2, b2, W3, b3, gamma, beta, mmean, mvar, out);
}

// round 9
// speedup vs baseline: 2.0692x; 1.0414x over previous
#include <cuda_runtime.h>
#include <cstdint>

#define S_LEN   200
#define D_DIM   64
#define TPB     128

// shared memory layout (floats). Xu stored at stride 64 with XOR-quad swizzle:
// physical quad index = qd ^ (row & 7)  (qd = d>>2). 16B aligned everywhere.
#define OFF_XU    0                        // 200*64 = 12800
#define OFF_M     (OFF_XU + S_LEN*64)      // 4096
#define OFF_C0    (OFF_M  + 64*64)         // 64
#define OFF_Q     (OFF_C0 + 64)            // 64
#define OFF_LG    (OFF_Q  + 64)            // 208 (200 used)
#define OFF_RED   (OFF_LG + 208)           // 40
#define OFF_POOL2 (OFF_RED + 40)           // 128 (2 groups x 64)
#define SMEM_FLOATS (OFF_POOL2 + 128)      // 17400
#define SMEM_BYTES  (SMEM_FLOATS * 4)      // 69600 B -> 3 CTAs/SM

typedef unsigned long long u64;

__device__ __forceinline__ u64 pack2(float lo, float hi) {
    u64 r;
    asm("mov.b64 %0, {%1, %2};" : "=l"(r) : "f"(lo), "f"(hi));
    return r;
}
__device__ __forceinline__ void unpack2(u64 v, float& lo, float& hi) {
    asm("mov.b64 {%0, %1}, %2;" : "=f"(lo), "=f"(hi) : "l"(v));
}
__device__ __forceinline__ void fma2(u64& acc, u64 a, u64 b) {
    asm("fma.rn.f32x2 %0, %1, %2, %0;" : "+l"(acc) : "l"(a), "l"(b));
}

__global__ void __launch_bounds__(TPB, 3)
din_user_repr_kernel(const float* __restrict__ em,
                     const float* __restrict__ eu,
                     const float* __restrict__ Xu,
                     const float* __restrict__ W1,
                     const float* __restrict__ b1,
                     const float* __restrict__ W2,
                     const float* __restrict__ b2,
                     const float* __restrict__ W3,
                     const float* __restrict__ b3,
                     const float* __restrict__ gamma,
                     const float* __restrict__ beta,
                     const float* __restrict__ mmean,
                     const float* __restrict__ mvar,
                     float* __restrict__ out)
{
    extern __shared__ float sm[];
    float* sXu   = sm + OFF_XU;
    float* sM    = sm + OFF_M;
    float* sC0   = sm + OFF_C0;
    float* sQ    = sm + OFF_Q;
    float* sLg   = sm + OFF_LG;
    float* sRed  = sm + OFF_RED;
    float* sPool2= sm + OFF_POOL2;

    const int b = blockIdx.x;
    const int t = threadIdx.x;

    // ---- stage 0: loads ----------------------------------------------------
    if (t < 64) sQ[t] = em[(size_t)b * 64 + t];

    {   // Xu tile: coalesced float4 reads -> swizzled smem (stride 64, quad XOR)
        const float4* Xg = (const float4*)(Xu + (size_t)b * S_LEN * D_DIM);
        for (int i = t; i < S_LEN * D_DIM / 4; i += TPB) {
            float4 v = Xg[i];
            int e   = i * 4;
            int row = e >> 6;
            int qd  = (e >> 2) & 15;
            int pq  = qd ^ (row & 7);
            *(float4*)(sXu + row * 64 + pq * 4) = v;
        }
    }
    __syncthreads();

    // ---- stage 1: per-row folded weights ------------------------------------
    // M[d][j] = W1[64+d][j] - W1[128+d][j] + q[d]*W1[192+d][j]
    for (int i = t; i < 64 * 64; i += TPB) {
        int d = i >> 6, j = i & 63;
        sM[i] = W1[(64 + d) * 64 + j] - W1[(128 + d) * 64 + j]
              + sQ[d] * W1[(192 + d) * 64 + j];
    }
    // c0[j] = b1[j] + sum_d q[d]*(W1[d][j] + W1[128+d][j])
    if (t < 64) {
        float acc = b1[t];
        #pragma unroll 4
        for (int d = 0; d < 64; d++)
            acc += sQ[d] * (W1[d * 64 + t] + W1[(128 + d) * 64 + t]);
        sC0[t] = acc;
    }
    __syncthreads();

    // ---- stage 2: MLP, 2 positions per thread (t, t+100), j in quarters -----
    if (t < 100) {
        u64 h2a[16], h2b[16];
        {   // init from b2 (global, broadcast LDG, L1-resident)
            const float4* b2v = (const float4*)b2;
            #pragma unroll
            for (int k = 0; k < 8; k++) {
                float4 v = __ldg(b2v + k);
                u64 p0 = pack2(v.x, v.y), p1 = pack2(v.z, v.w);
                h2a[2*k] = p0; h2a[2*k+1] = p1;
                h2b[2*k] = p0; h2b[2*k+1] = p1;
            }
        }

        const int r0 = t, r1 = t + 100;
        const float* x0b = sXu + r0 * 64;
        const float* x1b = sXu + r1 * 64;
        const int sw0 = (r0 & 7) << 2;   // quad swizzle (in floats)
        const int sw1 = (r1 & 7) << 2;
        const u64* Mb = (const u64*)sM;

        #pragma unroll
        for (int h = 0; h < 4; h++) {          // j-quarters [16h, 16h+16)
            // ---- layer 1 quarter: h1[16h..16h+15] for both positions ----
            u64 h1a[8], h1b[8];
            {
                const ulonglong2* c0v = (const ulonglong2*)((const u64*)sC0 + h * 8);
                #pragma unroll
                for (int k = 0; k < 4; k++) {
                    ulonglong2 c = c0v[k];
                    h1a[2*k] = c.x; h1a[2*k+1] = c.y;
                    h1b[2*k] = c.x; h1b[2*k+1] = c.y;
                }
            }
            const u64* mbase = Mb + h * 8;
            #pragma unroll 8
            for (int q = 0; q < 16; q++) {     // quads of d
                // swizzled, 16B-aligned, conflict-free row loads
                float4 va = *(const float4*)(x0b + (((q << 2) ^ sw0)));
                float4 vb = *(const float4*)(x1b + (((q << 2) ^ sw1)));
                const float fa[4] = {va.x, va.y, va.z, va.w};
                const float fb[4] = {vb.x, vb.y, vb.z, vb.w};
                #pragma unroll
                for (int dd = 0; dd < 4; dd++) {
                    u64 xa = pack2(fa[dd], fa[dd]);
                    u64 xb = pack2(fb[dd], fb[dd]);
                    const ulonglong2* mv = (const ulonglong2*)(mbase + (q * 4 + dd) * 32);
                    ulonglong2 m0 = mv[0];
                    ulonglong2 m1 = mv[1];
                    fma2(h1a[0], xa, m0.x); fma2(h1a[1], xa, m0.y);
                    fma2(h1a[2], xa, m1.x); fma2(h1a[3], xa, m1.y);
                    fma2(h1b[0], xb, m0.x); fma2(h1b[1], xb, m0.y);
                    fma2(h1b[2], xb, m1.x); fma2(h1b[3], xb, m1.y);
                    ulonglong2 m2 = mv[2];
                    ulonglong2 m3 = mv[3];
                    fma2(h1a[4], xa, m2.x); fma2(h1a[5], xa, m2.y);
                    fma2(h1a[6], xa, m3.x); fma2(h1a[7], xa, m3.y);
                    fma2(h1b[4], xb, m2.x); fma2(h1b[5], xb, m2.y);
                    fma2(h1b[6], xb, m3.x); fma2(h1b[7], xb, m3.y);
                }
            }

            // ---- layer 2 partial: relu(h1 quarter) @ W2 rows [16h..16h+16) ----
            // W2 read straight from global (broadcast LDG.128, L1-resident)
            const float4* w2g = (const float4*)(W2 + (h * 16) * 32);
            #pragma unroll
            for (int kk = 0; kk < 8; kk++) {
                float la, ha, lb, hb;
                unpack2(h1a[kk], la, ha);
                unpack2(h1b[kk], lb, hb);
                la = fmaxf(la, 0.0f); ha = fmaxf(ha, 0.0f);
                lb = fmaxf(lb, 0.0f); hb = fmaxf(hb, 0.0f);
                u64 ral = pack2(la, la), rah = pack2(ha, ha);
                u64 rbl = pack2(lb, lb), rbh = pack2(hb, hb);
                const float4* wa = w2g + (2 * kk)     * 8;  // row 16h+2kk
                const float4* wb = w2g + (2 * kk + 1) * 8;  // row 16h+2kk+1
                #pragma unroll
                for (int k = 0; k < 8; k++) {
                    float4 a4 = __ldg(wa + k);
                    float4 b4 = __ldg(wb + k);
                    u64 wax = pack2(a4.x, a4.y), way = pack2(a4.z, a4.w);
                    u64 wbx = pack2(b4.x, b4.y), wby = pack2(b4.z, b4.w);
                    fma2(h2a[2*k],   ral, wax); fma2(h2a[2*k+1], ral, way);
                    fma2(h2a[2*k],   rah, wbx); fma2(h2a[2*k+1], rah, wby);
                    fma2(h2b[2*k],   rbl, wax); fma2(h2b[2*k+1], rbl, way);
                    fma2(h2b[2*k],   rbh, wbx); fma2(h2b[2*k+1], rbh, wby);
                }
            }
        }

        // ---- layer 3: logits (W3/b3 via broadcast LDG) ----
        float bb3 = __ldg(b3);
        float lga = bb3, lgb = bb3;
        #pragma unroll
        for (int k = 0; k < 16; k++) {
            float w0 = __ldg(W3 + 2 * k);
            float w1 = __ldg(W3 + 2 * k + 1);
            float lo, hi;
            unpack2(h2a[k], lo, hi);
            lga += fmaxf(lo, 0.0f) * w0 + fmaxf(hi, 0.0f) * w1;
            unpack2(h2b[k], lo, hi);
            lgb += fmaxf(lo, 0.0f) * w0 + fmaxf(hi, 0.0f) * w1;
        }
        sLg[t]       = lga;
        sLg[t + 100] = lgb;
    }
    __syncthreads();

    // ---- stage 3: softmax over S --------------------------------------------
    const float NEG_INF = __int_as_float(0xff800000);
    float mx = NEG_INF;
    for (int i = t; i < S_LEN; i += TPB) mx = fmaxf(mx, sLg[i]);
    #pragma unroll
    for (int o = 16; o > 0; o >>= 1) mx = fmaxf(mx, __shfl_xor_sync(0xffffffffu, mx, o));
    if ((t & 31) == 0) sRed[t >> 5] = mx;
    __syncthreads();
    if (t == 0) {
        float m = sRed[0];
        #pragma unroll
        for (int w = 1; w < TPB / 32; w++) m = fmaxf(m, sRed[w]);
        sRed[32] = m;
    }
    __syncthreads();
    mx = sRed[32];

    float se = 0.0f;
    for (int i = t; i < S_LEN; i += TPB) {
        float v = __expf(sLg[i] - mx);
        sLg[i] = v;
        se += v;
    }
    #pragma unroll
    for (int o = 16; o > 0; o >>= 1) se += __shfl_xor_sync(0xffffffffu, se, o);
    if ((t & 31) == 0) sRed[t >> 5] = se;
    __syncthreads();
    if (t == 0) {
        float s = 0.0f;
        #pragma unroll
        for (int w = 0; w < TPB / 32; w++) s += sRed[w];
        sRed[33] = 1.0f / s;
    }
    __syncthreads();
    const float invSum = sRed[33];

    // ---- stage 4: weighted pool (swizzled column reads, conflict-free) -------
    {
        const int g  = t >> 6;          // 0 or 1
        const int d  = t & 63;
        const int qd = d >> 2, dl = d & 3;
        const int s0 = g * 100;
        float acc = 0.0f;
        #pragma unroll 4
        for (int s = s0; s < s0 + 100; s++) {
            int pq = qd ^ (s & 7);
            acc += sLg[s] * sXu[s * 64 + pq * 4 + dl];
        }
        sPool2[t] = acc;
    }
    __syncthreads();

    // ---- stage 5: BN + concat epilogue ---------------------------------------
    float* ob = out + (size_t)b * 192;
    for (int i = t; i < 192; i += TPB) {
        if (i < 128) {
            float v = (i < 64) ? (sPool2[i] + sPool2[64 + i]) * invSum
                               : sQ[i - 64];
            ob[i] = (v - mmean[i]) * rsqrtf(mvar[i] + 1e-3f) * gamma[i] + beta[i];
        } else {
            ob[i] = eu[(size_t)b * 64 + (i - 128)];
        }
    }
}

extern "C" void kernel_launch(void* const* d_in, const int* in_sizes, int n_in,
                              void* d_out, int out_size)
{
    const float* em    = (const float*)d_in[0];
    const float* eu    = (const float*)d_in[1];
    const float* Xu    = (const float*)d_in[2];
    const float* W1    = (const float*)d_in[3];
    const float* b1    = (const float*)d_in[4];
    const float* W2    = (const float*)d_in[5];
    const float* b2    = (const float*)d_in[6];
    const float* W3    = (const float*)d_in[7];
    const float* b3    = (const float*)d_in[8];
    const float* gamma = (const float*)d_in[9];
    const float* beta  = (const float*)d_in[10];
    const float* mmean = (const float*)d_in[11];
    const float* mvar  = (const float*)d_in[12];
    float* out = (float*)d_out;

    const int B = in_sizes[0] / D_DIM;

    cudaFuncSetAttribute(din_user_repr_kernel,
                         cudaFuncAttributeMaxDynamicSharedMemorySize, SMEM_BYTES);
    din_user_repr_kernel<<<B, TPB, SMEM_BYTES>>>(
        em, eu, Xu, W1, b1, W2, b2, W3, b3, gamma, beta, mmean, mvar, out);
}

// round 12
// speedup vs baseline: 2.2749x; 1.0994x over previous
#include <cuda_runtime.h>
#include <cuda_fp16.h>
#include <cstdint>

#define TPB    128
#define S_LEN  200

// ---- smem layout (bytes). fp16 tiles: 128B rows, SW128 swizzle ----
#define SB_XH   0            // X hi : 208 rows x 128B (fp16[208][64])
#define SB_XL   26624        // X lo
#define SB_MH   53248        // M^T hi: 64 rows x 128B (fp16[64][64])
#define SB_ML   61440        // M^T lo
#define SB_WH   69632        // W2^T hi: 32 rows x 128B (fp16[32][64])
#define SB_WL   73728        // W2^T lo
#define SB_F    77824        // float region
#define SMEM_BYTES (SB_F + 2560)   // 80384 B -> 2 CTAs/SM

// float-region offsets (floats)
#define F_C0    0     // 64
#define F_Q     64    // 64
#define F_B2    128   // 32
#define F_W3    160   // 32
#define F_LG    192   // 208
#define F_RED   400   // 40
#define F_POOL  440   // 128

#define SWZ(o) ((o) ^ (((o) >> 3) & 0x70))

// ---------------- helpers ----------------
__device__ __forceinline__ uint32_t smem_u32(const void* p) {
    uint32_t a;
    asm("{ .reg .u64 t; cvta.to.shared.u64 t, %1; cvt.u32.u64 %0, t; }" : "=r"(a) : "l"(p));
    return a;
}
__device__ __forceinline__ void ldsm4(uint32_t& r0, uint32_t& r1, uint32_t& r2, uint32_t& r3,
                                      uint32_t addr) {
    asm volatile("ldmatrix.sync.aligned.m8n8.x4.shared.b16 {%0,%1,%2,%3}, [%4];"
                 : "=r"(r0), "=r"(r1), "=r"(r2), "=r"(r3) : "r"(addr));
}
__device__ __forceinline__ void mma16816(float& d0, float& d1, float& d2, float& d3,
                                         uint32_t a0, uint32_t a1, uint32_t a2, uint32_t a3,
                                         uint32_t b0, uint32_t b1) {
    asm volatile("mma.sync.aligned.m16n8k16.row.col.f32.f16.f16.f32 "
                 "{%0,%1,%2,%3}, {%4,%5,%6,%7}, {%8,%9}, {%0,%1,%2,%3};"
                 : "+f"(d0), "+f"(d1), "+f"(d2), "+f"(d3)
                 : "r"(a0), "r"(a1), "r"(a2), "r"(a3), "r"(b0), "r"(b1));
}
__device__ __forceinline__ uint32_t packh(__half a, __half b) {
    __half2 h = __halves2half2(a, b);
    return *reinterpret_cast<uint32_t*>(&h);
}
__device__ __forceinline__ void split2(float v0, float v1, uint32_t& hi, uint32_t& lo) {
    __half h0 = __float2half_rn(v0), h1 = __float2half_rn(v1);
    float r0 = v0 - __half2float(h0), r1 = v1 - __half2float(h1);
    hi = packh(h0, h1);
    lo = packh(__float2half_rn(r0), __float2half_rn(r1));
}

// ---------------- kernel ----------------
__global__ void __launch_bounds__(TPB, 2)
din_user_repr_kernel(const float* __restrict__ em,
                     const float* __restrict__ eu,
                     const float* __restrict__ Xu,
                     const float* __restrict__ W1,
                     const float* __restrict__ b1,
                     const float* __restrict__ W2,
                     const float* __restrict__ b2,
                     const float* __restrict__ W3,
                     const float* __restrict__ b3,
                     const float* __restrict__ gamma,
                     const float* __restrict__ beta,
                     const float* __restrict__ mmean,
                     const float* __restrict__ mvar,
                     float* __restrict__ out)
{
    extern __shared__ char smemc[];
    float* sF   = (float*)(smemc + SB_F);
    float* sC0  = sF + F_C0;
    float* sQ   = sF + F_Q;
    float* sB2  = sF + F_B2;
    float* sW3  = sF + F_W3;
    float* sLg  = sF + F_LG;
    float* sRed = sF + F_RED;
    float* sPool= sF + F_POOL;

    const int b   = blockIdx.x;
    const int t   = threadIdx.x;
    const int wid = t >> 5;
    const int lid = t & 31;
    const uint32_t sbase = smem_u32(smemc);

    // ---- stage 0: loads + fp16 split conversions ---------------------------
    if (t < 64) sQ[t] = em[(size_t)b * 64 + t];
    if (t >= 64 && t < 96)  sB2[t - 64] = b2[t - 64];
    if (t >= 96 && t < 128) sW3[t - 96] = W3[t - 96];

    {   // X -> (Xh, Xl) fp16, SW128-swizzled 128B rows
        const float2* Xg2 = (const float2*)(Xu + (size_t)b * S_LEN * 64);
        for (int i = t; i < S_LEN * 32; i += TPB) {
            float2 v = Xg2[i];
            int row = i >> 5, p = i & 31;
            uint32_t hi, lo;
            split2(v.x, v.y, hi, lo);
            uint32_t off = SWZ((uint32_t)(row * 128 + p * 4));
            *(uint32_t*)(smemc + SB_XH + off) = hi;
            *(uint32_t*)(smemc + SB_XL + off) = lo;
        }
        // zero pad rows 200..207 (both tiles)
        for (int i = t; i < 512; i += TPB) {
            int tile = i >> 8, j = i & 255;
            int row = 200 + (j >> 5), p = j & 31;
            uint32_t off = SWZ((uint32_t)(row * 128 + p * 4));
            *(uint32_t*)(smemc + (tile ? SB_XL : SB_XH) + off) = 0;
        }
    }
    {   // W2^T -> hi/lo (W2T[n][k] = W2[k][n])
        for (int i = t; i < 64 * 32; i += TPB) {
            int k = i >> 5, n = i & 31;
            float w = W2[k * 32 + n];
            __half wh = __float2half_rn(w);
            __half wl = __float2half_rn(w - __half2float(wh));
            uint32_t off = SWZ((uint32_t)(n * 128 + k * 2));
            *(__half*)(smemc + SB_WH + off) = wh;
            *(__half*)(smemc + SB_WL + off) = wl;
        }
    }
    __syncthreads();   // sQ visible

    // ---- stage 1: folded weights M^T hi/lo + c0 -----------------------------
    for (int i = t; i < 64 * 64; i += TPB) {
        int d = i >> 6, j = i & 63;
        float m = W1[(64 + d) * 64 + j] - W1[(128 + d) * 64 + j]
                + sQ[d] * W1[(192 + d) * 64 + j];
        __half mh = __float2half_rn(m);
        __half ml = __float2half_rn(m - __half2float(mh));
        uint32_t off = SWZ((uint32_t)(j * 128 + d * 2));   // M^T[j][d]
        *(__half*)(smemc + SB_MH + off) = mh;
        *(__half*)(smemc + SB_ML + off) = ml;
    }
    if (t < 64) {
        float acc = b1[t];
        #pragma unroll 4
        for (int d = 0; d < 64; d++)
            acc += sQ[d] * (W1[d * 64 + t] + W1[(128 + d) * 64 + t]);
        sC0[t] = acc;
    }
    __syncthreads();

    // ---- stage 2: tensor-core MLP, m-tiles round-robin over warps -----------
    {
        const int i8  = lid & 7;
        const int sel = lid >> 3;
        const int tig = lid & 3;
        const int gid = lid >> 2;
        const float bb3 = __ldg(b3);

        for (int mt = wid; mt < 13; mt += 4) {
            const int m0 = mt * 16;

            // --- A frags for X hi/lo (4 k-chunks) ---
            uint32_t Ah[4][4], Al[4][4];
            #pragma unroll
            for (int kc = 0; kc < 4; kc++) {
                uint32_t off = SWZ((uint32_t)((m0 + ((sel & 1) << 3) + i8) * 128
                                              + kc * 32 + ((sel & 2) << 3)));
                ldsm4(Ah[kc][0], Ah[kc][1], Ah[kc][2], Ah[kc][3], sbase + SB_XH + off);
                ldsm4(Al[kc][0], Al[kc][1], Al[kc][2], Al[kc][3], sbase + SB_XL + off);
            }

            // --- layer 1: C1[8 n-tiles] = Xh@Mh + Xh@Ml + Xl@Mh ---
            float c1[8][4];
            #pragma unroll
            for (int nt = 0; nt < 8; nt++) {
                c1[nt][0] = 0.f; c1[nt][1] = 0.f; c1[nt][2] = 0.f; c1[nt][3] = 0.f;
            }
            #pragma unroll
            for (int kc = 0; kc < 4; kc++) {
                uint32_t Bh[4][4], Bl[4][4];
                #pragma unroll
                for (int q = 0; q < 4; q++) {   // covers n-tiles 2q, 2q+1
                    uint32_t off = SWZ((uint32_t)((16 * q + ((sel >> 1) << 3) + i8) * 128
                                                  + kc * 32 + ((sel & 1) << 4)));
                    ldsm4(Bh[q][0], Bh[q][1], Bh[q][2], Bh[q][3], sbase + SB_MH + off);
                    ldsm4(Bl[q][0], Bl[q][1], Bl[q][2], Bl[q][3], sbase + SB_ML + off);
                }
                #pragma unroll
                for (int nt = 0; nt < 8; nt++) {
                    uint32_t bh0 = Bh[nt >> 1][(nt & 1) * 2], bh1 = Bh[nt >> 1][(nt & 1) * 2 + 1];
                    uint32_t bl0 = Bl[nt >> 1][(nt & 1) * 2], bl1 = Bl[nt >> 1][(nt & 1) * 2 + 1];
                    mma16816(c1[nt][0], c1[nt][1], c1[nt][2], c1[nt][3],
                             Ah[kc][0], Ah[kc][1], Ah[kc][2], Ah[kc][3], bh0, bh1);
                    mma16816(c1[nt][0], c1[nt][1], c1[nt][2], c1[nt][3],
                             Ah[kc][0], Ah[kc][1], Ah[kc][2], Ah[kc][3], bl0, bl1);
                    mma16816(c1[nt][0], c1[nt][1], c1[nt][2], c1[nt][3],
                             Al[kc][0], Al[kc][1], Al[kc][2], Al[kc][3], bh0, bh1);
                }
            }

            // --- epilogue 1: +c0, relu, split -> layer-2 A frags (registers) ---
            // C frag (m16n8) == A frag k8-chunk layout: a0=pk(d0,d1), a1=pk(d2,d3)
            uint32_t A2h[4][4], A2l[4][4];
            #pragma unroll
            for (int nt = 0; nt < 8; nt++) {
                float2 c0p = *(const float2*)&sC0[8 * nt + 2 * tig];
                float v0 = fmaxf(c1[nt][0] + c0p.x, 0.f);
                float v1 = fmaxf(c1[nt][1] + c0p.y, 0.f);
                float v2 = fmaxf(c1[nt][2] + c0p.x, 0.f);
                float v3 = fmaxf(c1[nt][3] + c0p.y, 0.f);
                int kc2 = nt >> 1, r = (nt & 1) * 2;
                split2(v0, v1, A2h[kc2][r],     A2l[kc2][r]);
                split2(v2, v3, A2h[kc2][r + 1], A2l[kc2][r + 1]);
            }

            // --- layer 2: C2[4 n-tiles] = A2h@W2h + A2h@W2l + A2l@W2h ---
            float c2[4][4];
            #pragma unroll
            for (int nt = 0; nt < 4; nt++) {
                c2[nt][0] = 0.f; c2[nt][1] = 0.f; c2[nt][2] = 0.f; c2[nt][3] = 0.f;
            }
            #pragma unroll
            for (int kc = 0; kc < 4; kc++) {
                uint32_t Wh[2][4], Wl[2][4];
                #pragma unroll
                for (int q = 0; q < 2; q++) {
                    uint32_t off = SWZ((uint32_t)((16 * q + ((sel >> 1) << 3) + i8) * 128
                                                  + kc * 32 + ((sel & 1) << 4)));
                    ldsm4(Wh[q][0], Wh[q][1], Wh[q][2], Wh[q][3], sbase + SB_WH + off);
                    ldsm4(Wl[q][0], Wl[q][1], Wl[q][2], Wl[q][3], sbase + SB_WL + off);
                }
                #pragma unroll
                for (int nt = 0; nt < 4; nt++) {
                    uint32_t bh0 = Wh[nt >> 1][(nt & 1) * 2], bh1 = Wh[nt >> 1][(nt & 1) * 2 + 1];
                    uint32_t bl0 = Wl[nt >> 1][(nt & 1) * 2], bl1 = Wl[nt >> 1][(nt & 1) * 2 + 1];
                    mma16816(c2[nt][0], c2[nt][1], c2[nt][2], c2[nt][3],
                             A2h[kc][0], A2h[kc][1], A2h[kc][2], A2h[kc][3], bh0, bh1);
                    mma16816(c2[nt][0], c2[nt][1], c2[nt][2], c2[nt][3],
                             A2h[kc][0], A2h[kc][1], A2h[kc][2], A2h[kc][3], bl0, bl1);
                    mma16816(c2[nt][0], c2[nt][1], c2[nt][2], c2[nt][3],
                             A2l[kc][0], A2l[kc][1], A2l[kc][2], A2l[kc][3], bh0, bh1);
                }
            }

            // --- epilogue 2: +b2, relu, dot W3 -> logits ---
            float lg0 = 0.f, lg1 = 0.f;
            #pragma unroll
            for (int nt = 0; nt < 4; nt++) {
                int j0 = 8 * nt + 2 * tig;
                float2 b2p = *(const float2*)&sB2[j0];
                float2 w3p = *(const float2*)&sW3[j0];
                lg0 += fmaxf(c2[nt][0] + b2p.x, 0.f) * w3p.x
                     + fmaxf(c2[nt][1] + b2p.y, 0.f) * w3p.y;
                lg1 += fmaxf(c2[nt][2] + b2p.x, 0.f) * w3p.x
                     + fmaxf(c2[nt][3] + b2p.y, 0.f) * w3p.y;
            }
            lg0 += __shfl_xor_sync(0xffffffffu, lg0, 1);
            lg0 += __shfl_xor_sync(0xffffffffu, lg0, 2);
            lg1 += __shfl_xor_sync(0xffffffffu, lg1, 1);
            lg1 += __shfl_xor_sync(0xffffffffu, lg1, 2);
            if (tig == 0) {
                int r0 = m0 + gid, r1 = m0 + gid + 8;
                if (r0 < S_LEN) sLg[r0] = lg0 + bb3;
                if (r1 < S_LEN) sLg[r1] = lg1 + bb3;
            }
        }
    }
    __syncthreads();

    // ---- stage 3: softmax over S --------------------------------------------
    const float NEG_INF = __int_as_float(0xff800000);
    float mx = NEG_INF;
    for (int i = t; i < S_LEN; i += TPB) mx = fmaxf(mx, sLg[i]);
    #pragma unroll
    for (int o = 16; o > 0; o >>= 1) mx = fmaxf(mx, __shfl_xor_sync(0xffffffffu, mx, o));
    if (lid == 0) sRed[wid] = mx;
    __syncthreads();
    if (t == 0) {
        float m = sRed[0];
        #pragma unroll
        for (int w = 1; w < TPB / 32; w++) m = fmaxf(m, sRed[w]);
        sRed[32] = m;
    }
    __syncthreads();
    mx = sRed[32];

    float se = 0.0f;
    for (int i = t; i < S_LEN; i += TPB) {
        float v = __expf(sLg[i] - mx);
        sLg[i] = v;
        se += v;
    }
    #pragma unroll
    for (int o = 16; o > 0; o >>= 1) se += __shfl_xor_sync(0xffffffffu, se, o);
    if (lid == 0) sRed[wid] = se;
    __syncthreads();
    if (t == 0) {
        float s = 0.0f;
        #pragma unroll
        for (int w = 0; w < TPB / 32; w++) s += sRed[w];
        sRed[33] = 1.0f / s;
    }
    __syncthreads();
    const float invSum = sRed[33];

    // ---- stage 4: weighted pool (x = xh + xl from fp16 tiles) ----------------
    {
        const int g = t >> 6, d = t & 63;
        const int s0 = g * 100;
        float acc = 0.0f;
        #pragma unroll 4
        for (int s = s0; s < s0 + 100; s++) {
            uint32_t off = SWZ((uint32_t)(s * 128 + d * 2));
            float xh = __half2float(*(__half*)(smemc + SB_XH + off));
            float xl = __half2float(*(__half*)(smemc + SB_XL + off));
            acc += sLg[s] * (xh + xl);
        }
        sPool[t] = acc;
    }
    __syncthreads();

    // ---- stage 5: BN + concat epilogue ----------------------------------------
    float* ob = out + (size_t)b * 192;
    for (int i = t; i < 192; i += TPB) {
        if (i < 128) {
            float v = (i < 64) ? (sPool[i] + sPool[64 + i]) * invSum
                               : sQ[i - 64];
            ob[i] = (v - mmean[i]) * rsqrtf(mvar[i] + 1e-3f) * gamma[i] + beta[i];
        } else {
            ob[i] = eu[(size_t)b * 64 + (i - 128)];
        }
    }
}

extern "C" void kernel_launch(void* const* d_in, const int* in_sizes, int n_in,
                              void* d_out, int out_size)
{
    const float* em    = (const float*)d_in[0];
    const float* eu    = (const float*)d_in[1];
    const float* Xu    = (const float*)d_in[2];
    const float* W1    = (const float*)d_in[3];
    const float* b1    = (const float*)d_in[4];
    const float* W2    = (const float*)d_in[5];
    const float* b2    = (const float*)d_in[6];
    const float* W3    = (const float*)d_in[7];
    const float* b3    = (const float*)d_in[8];
    const float* gamma = (const float*)d_in[9];
    const float* beta  = (const float*)d_in[10];
    const float* mmean = (const float*)d_in[11];
    const float* mvar  = (const float*)d_in[12];
    float* out = (float*)d_out;

    const int B = in_sizes[0] / 64;

    cudaFuncSetAttribute(din_user_repr_kernel,
                         cudaFuncAttributeMaxDynamicSharedMemorySize, SMEM_BYTES);
    din_user_repr_kernel<<<B, TPB, SMEM_BYTES>>>(
        em, eu, Xu, W1, b1, W2, b2, W3, b3, gamma, beta, mmean, mvar, out);
}

// round 13
// speedup vs baseline: 2.8076x; 1.2342x over previous
#include <cuda_runtime.h>
#include <cuda_fp16.h>
#include <cstdint>

#define TPB    256
#define S_LEN  200

// ---- smem layout (bytes). fp16 tiles: 128B rows, SW128 swizzle ----
#define SB_XH   0            // X hi : 208 rows x 128B (fp16[208][64])
#define SB_XL   26624        // X lo
#define SB_MH   53248        // M^T hi: 64 rows x 128B (fp16[64][64])
#define SB_ML   61440        // M^T lo
#define SB_WH   69632        // W2^T hi: 32 rows x 128B (fp16[32][64])
#define SB_WL   73728        // W2^T lo
#define SB_F    77824        // float region
#define SMEM_BYTES (SB_F + 3072)   // 80896 B -> 2 CTAs/SM

// float-region offsets (floats)
#define F_C0    0     // 64
#define F_Q     64    // 64
#define F_B2    128   // 32
#define F_W3    160   // 32
#define F_LG    192   // 208
#define F_RED   400   // 48
#define F_POOL  448   // 256 (4 groups x 64; also c0 scratch)

#define SWZ(o) ((o) ^ (((o) >> 3) & 0x70))

// ---------------- helpers ----------------
__device__ __forceinline__ uint32_t smem_u32(const void* p) {
    uint32_t a;
    asm("{ .reg .u64 t; cvta.to.shared.u64 t, %1; cvt.u32.u64 %0, t; }" : "=r"(a) : "l"(p));
    return a;
}
__device__ __forceinline__ void ldsm4(uint32_t& r0, uint32_t& r1, uint32_t& r2, uint32_t& r3,
                                      uint32_t addr) {
    asm volatile("ldmatrix.sync.aligned.m8n8.x4.shared.b16 {%0,%1,%2,%3}, [%4];"
                 : "=r"(r0), "=r"(r1), "=r"(r2), "=r"(r3) : "r"(addr));
}
__device__ __forceinline__ void mma16816(float& d0, float& d1, float& d2, float& d3,
                                         uint32_t a0, uint32_t a1, uint32_t a2, uint32_t a3,
                                         uint32_t b0, uint32_t b1) {
    asm volatile("mma.sync.aligned.m16n8k16.row.col.f32.f16.f16.f32 "
                 "{%0,%1,%2,%3}, {%4,%5,%6,%7}, {%8,%9}, {%0,%1,%2,%3};"
                 : "+f"(d0), "+f"(d1), "+f"(d2), "+f"(d3)
                 : "r"(a0), "r"(a1), "r"(a2), "r"(a3), "r"(b0), "r"(b1));
}
__device__ __forceinline__ uint32_t packh(__half a, __half b) {
    __half2 h = __halves2half2(a, b);
    return *reinterpret_cast<uint32_t*>(&h);
}
__device__ __forceinline__ void split2(float v0, float v1, uint32_t& hi, uint32_t& lo) {
    __half h0 = __float2half_rn(v0), h1 = __float2half_rn(v1);
    float r0 = v0 - __half2float(h0), r1 = v1 - __half2float(h1);
    hi = packh(h0, h1);
    lo = packh(__float2half_rn(r0), __float2half_rn(r1));
}

// ---------------- kernel ----------------
__global__ void __launch_bounds__(TPB, 2)
din_user_repr_kernel(const float* __restrict__ em,
                     const float* __restrict__ eu,
                     const float* __restrict__ Xu,
                     const float* __restrict__ W1,
                     const float* __restrict__ b1,
                     const float* __restrict__ W2,
                     const float* __restrict__ b2,
                     const float* __restrict__ W3,
                     const float* __restrict__ b3,
                     const float* __restrict__ gamma,
                     const float* __restrict__ beta,
                     const float* __restrict__ mmean,
                     const float* __restrict__ mvar,
                     float* __restrict__ out)
{
    extern __shared__ char smemc[];
    float* sF   = (float*)(smemc + SB_F);
    float* sC0  = sF + F_C0;
    float* sQ   = sF + F_Q;
    float* sB2  = sF + F_B2;
    float* sW3  = sF + F_W3;
    float* sLg  = sF + F_LG;
    float* sRed = sF + F_RED;
    float* sPool= sF + F_POOL;

    const int b   = blockIdx.x;
    const int t   = threadIdx.x;
    const int wid = t >> 5;
    const int lid = t & 31;
    const uint32_t sbase = smem_u32(smemc);

    // ---- stage 0: loads + fp16 split conversions ---------------------------
    if (t < 64)                 sQ[t]       = em[(size_t)b * 64 + t];
    else if (t < 96)            sB2[t - 64] = b2[t - 64];
    else if (t < 128)           sW3[t - 96] = W3[t - 96];

    {   // X -> (Xh, Xl) fp16, SW128-swizzled 128B rows (float4 loads)
        const float4* Xg4 = (const float4*)(Xu + (size_t)b * S_LEN * 64);
        for (int i = t; i < S_LEN * 16; i += TPB) {
            float4 v = Xg4[i];
            int row = i >> 4, p = i & 15;          // 16 float4 per 64-float row
            uint32_t h0, l0, h1, l1;
            split2(v.x, v.y, h0, l0);
            split2(v.z, v.w, h1, l1);
            uint32_t off = SWZ((uint32_t)(row * 128 + p * 8));
            *(uint2*)(smemc + SB_XH + off) = make_uint2(h0, h1);
            *(uint2*)(smemc + SB_XL + off) = make_uint2(l0, l1);
        }
        // zero pad rows 200..207 (both tiles)
        for (int i = t; i < 512; i += TPB) {
            int tile = i >> 8, j = i & 255;
            int row = 200 + (j >> 5), p = j & 31;
            uint32_t off = SWZ((uint32_t)(row * 128 + p * 4));
            *(uint32_t*)(smemc + (tile ? SB_XL : SB_XH) + off) = 0;
        }
    }
    {   // W2^T -> hi/lo (W2T[n][k] = W2[k][n])
        for (int i = t; i < 64 * 32; i += TPB) {
            int k = i >> 5, n = i & 31;
            float w = W2[k * 32 + n];
            __half wh = __float2half_rn(w);
            __half wl = __float2half_rn(w - __half2float(wh));
            uint32_t off = SWZ((uint32_t)(n * 128 + k * 2));
            *(__half*)(smemc + SB_WH + off) = wh;
            *(__half*)(smemc + SB_WL + off) = wl;
        }
    }
    __syncthreads();   // sQ visible

    // ---- stage 1: folded weights M^T hi/lo + c0 (2-way parallel) ------------
    for (int i = t; i < 64 * 64; i += TPB) {
        int d = i >> 6, j = i & 63;
        float m = W1[(64 + d) * 64 + j] - W1[(128 + d) * 64 + j]
                + sQ[d] * W1[(192 + d) * 64 + j];
        __half mh = __float2half_rn(m);
        __half ml = __float2half_rn(m - __half2float(mh));
        uint32_t off = SWZ((uint32_t)(j * 128 + d * 2));   // M^T[j][d]
        *(__half*)(smemc + SB_MH + off) = mh;
        *(__half*)(smemc + SB_ML + off) = ml;
    }
    if (t < 128) {   // c0 partials: thread (j, half) sums 32 d's (sPool scratch)
        int j = t & 63, hf = t >> 6;
        int d0 = hf * 32;
        float acc = hf ? 0.0f : b1[j];
        #pragma unroll 4
        for (int d = d0; d < d0 + 32; d++)
            acc += sQ[d] * (W1[d * 64 + j] + W1[(128 + d) * 64 + j]);
        sPool[t] = acc;
    }
    __syncthreads();
    if (t < 64) sC0[t] = sPool[t] + sPool[t + 64];
    __syncthreads();

    // ---- stage 2: tensor-core MLP, 13 m-tiles over 8 warps ------------------
    {
        const int i8  = lid & 7;
        const int sel = lid >> 3;
        const int tig = lid & 3;
        const int gid = lid >> 2;
        const float bb3 = __ldg(b3);

        for (int mt = wid; mt < 13; mt += 8) {
            const int m0 = mt * 16;

            // --- A frags for X hi/lo (4 k-chunks) ---
            uint32_t Ah[4][4], Al[4][4];
            #pragma unroll
            for (int kc = 0; kc < 4; kc++) {
                uint32_t off = SWZ((uint32_t)((m0 + ((sel & 1) << 3) + i8) * 128
                                              + kc * 32 + ((sel & 2) << 3)));
                ldsm4(Ah[kc][0], Ah[kc][1], Ah[kc][2], Ah[kc][3], sbase + SB_XH + off);
                ldsm4(Al[kc][0], Al[kc][1], Al[kc][2], Al[kc][3], sbase + SB_XL + off);
            }

            // --- layer 1: C1[8 n-tiles] = Xh@Mh + Xh@Ml + Xl@Mh ---
            float c1[8][4];
            #pragma unroll
            for (int nt = 0; nt < 8; nt++) {
                c1[nt][0] = 0.f; c1[nt][1] = 0.f; c1[nt][2] = 0.f; c1[nt][3] = 0.f;
            }
            #pragma unroll
            for (int kc = 0; kc < 4; kc++) {
                uint32_t Bh[4][4], Bl[4][4];
                #pragma unroll
                for (int q = 0; q < 4; q++) {   // covers n-tiles 2q, 2q+1
                    uint32_t off = SWZ((uint32_t)((16 * q + ((sel >> 1) << 3) + i8) * 128
                                                  + kc * 32 + ((sel & 1) << 4)));
                    ldsm4(Bh[q][0], Bh[q][1], Bh[q][2], Bh[q][3], sbase + SB_MH + off);
                    ldsm4(Bl[q][0], Bl[q][1], Bl[q][2], Bl[q][3], sbase + SB_ML + off);
                }
                #pragma unroll
                for (int nt = 0; nt < 8; nt++) {
                    uint32_t bh0 = Bh[nt >> 1][(nt & 1) * 2], bh1 = Bh[nt >> 1][(nt & 1) * 2 + 1];
                    uint32_t bl0 = Bl[nt >> 1][(nt & 1) * 2], bl1 = Bl[nt >> 1][(nt & 1) * 2 + 1];
                    mma16816(c1[nt][0], c1[nt][1], c1[nt][2], c1[nt][3],
                             Ah[kc][0], Ah[kc][1], Ah[kc][2], Ah[kc][3], bh0, bh1);
                    mma16816(c1[nt][0], c1[nt][1], c1[nt][2], c1[nt][3],
                             Ah[kc][0], Ah[kc][1], Ah[kc][2], Ah[kc][3], bl0, bl1);
                    mma16816(c1[nt][0], c1[nt][1], c1[nt][2], c1[nt][3],
                             Al[kc][0], Al[kc][1], Al[kc][2], Al[kc][3], bh0, bh1);
                }
            }

            // --- epilogue 1: +c0, relu, split -> layer-2 A frags (registers) ---
            uint32_t A2h[4][4], A2l[4][4];
            #pragma unroll
            for (int nt = 0; nt < 8; nt++) {
                float2 c0p = *(const float2*)&sC0[8 * nt + 2 * tig];
                float v0 = fmaxf(c1[nt][0] + c0p.x, 0.f);
                float v1 = fmaxf(c1[nt][1] + c0p.y, 0.f);
                float v2 = fmaxf(c1[nt][2] + c0p.x, 0.f);
                float v3 = fmaxf(c1[nt][3] + c0p.y, 0.f);
                int kc2 = nt >> 1, r = (nt & 1) * 2;
                split2(v0, v1, A2h[kc2][r],     A2l[kc2][r]);
                split2(v2, v3, A2h[kc2][r + 1], A2l[kc2][r + 1]);
            }

            // --- layer 2: C2[4 n-tiles] = A2h@W2h + A2h@W2l + A2l@W2h ---
            float c2[4][4];
            #pragma unroll
            for (int nt = 0; nt < 4; nt++) {
                c2[nt][0] = 0.f; c2[nt][1] = 0.f; c2[nt][2] = 0.f; c2[nt][3] = 0.f;
            }
            #pragma unroll
            for (int kc = 0; kc < 4; kc++) {
                uint32_t Wh[2][4], Wl[2][4];
                #pragma unroll
                for (int q = 0; q < 2; q++) {
                    uint32_t off = SWZ((uint32_t)((16 * q + ((sel >> 1) << 3) + i8) * 128
                                                  + kc * 32 + ((sel & 1) << 4)));
                    ldsm4(Wh[q][0], Wh[q][1], Wh[q][2], Wh[q][3], sbase + SB_WH + off);
                    ldsm4(Wl[q][0], Wl[q][1], Wl[q][2], Wl[q][3], sbase + SB_WL + off);
                }
                #pragma unroll
                for (int nt = 0; nt < 4; nt++) {
                    uint32_t bh0 = Wh[nt >> 1][(nt & 1) * 2], bh1 = Wh[nt >> 1][(nt & 1) * 2 + 1];
                    uint32_t bl0 = Wl[nt >> 1][(nt & 1) * 2], bl1 = Wl[nt >> 1][(nt & 1) * 2 + 1];
                    mma16816(c2[nt][0], c2[nt][1], c2[nt][2], c2[nt][3],
                             A2h[kc][0], A2h[kc][1], A2h[kc][2], A2h[kc][3], bh0, bh1);
                    mma16816(c2[nt][0], c2[nt][1], c2[nt][2], c2[nt][3],
                             A2h[kc][0], A2h[kc][1], A2h[kc][2], A2h[kc][3], bl0, bl1);
                    mma16816(c2[nt][0], c2[nt][1], c2[nt][2], c2[nt][3],
                             A2l[kc][0], A2l[kc][1], A2l[kc][2], A2l[kc][3], bh0, bh1);
                }
            }

            // --- epilogue 2: +b2, relu, dot W3 -> logits ---
            float lg0 = 0.f, lg1 = 0.f;
            #pragma unroll
            for (int nt = 0; nt < 4; nt++) {
                int j0 = 8 * nt + 2 * tig;
                float2 b2p = *(const float2*)&sB2[j0];
                float2 w3p = *(const float2*)&sW3[j0];
                lg0 += fmaxf(c2[nt][0] + b2p.x, 0.f) * w3p.x
                     + fmaxf(c2[nt][1] + b2p.y, 0.f) * w3p.y;
                lg1 += fmaxf(c2[nt][2] + b2p.x, 0.f) * w3p.x
                     + fmaxf(c2[nt][3] + b2p.y, 0.f) * w3p.y;
            }
            lg0 += __shfl_xor_sync(0xffffffffu, lg0, 1);
            lg0 += __shfl_xor_sync(0xffffffffu, lg0, 2);
            lg1 += __shfl_xor_sync(0xffffffffu, lg1, 1);
            lg1 += __shfl_xor_sync(0xffffffffu, lg1, 2);
            if (tig == 0) {
                int r0 = m0 + gid, r1 = m0 + gid + 8;
                if (r0 < S_LEN) sLg[r0] = lg0 + bb3;
                if (r1 < S_LEN) sLg[r1] = lg1 + bb3;
            }
        }
    }
    __syncthreads();

    // ---- stage 3: softmax over S --------------------------------------------
    const float NEG_INF = __int_as_float(0xff800000);
    float mx = NEG_INF;
    for (int i = t; i < S_LEN; i += TPB) mx = fmaxf(mx, sLg[i]);
    #pragma unroll
    for (int o = 16; o > 0; o >>= 1) mx = fmaxf(mx, __shfl_xor_sync(0xffffffffu, mx, o));
    if (lid == 0) sRed[wid] = mx;
    __syncthreads();
    if (t == 0) {
        float m = sRed[0];
        #pragma unroll
        for (int w = 1; w < TPB / 32; w++) m = fmaxf(m, sRed[w]);
        sRed[32] = m;
    }
    __syncthreads();
    mx = sRed[32];

    float se = 0.0f;
    for (int i = t; i < S_LEN; i += TPB) {
        float v = __expf(sLg[i] - mx);
        sLg[i] = v;
        se += v;
    }
    #pragma unroll
    for (int o = 16; o > 0; o >>= 1) se += __shfl_xor_sync(0xffffffffu, se, o);
    if (lid == 0) sRed[wid] = se;
    __syncthreads();
    if (t == 0) {
        float s = 0.0f;
        #pragma unroll
        for (int w = 0; w < TPB / 32; w++) s += sRed[w];
        sRed[33] = 1.0f / s;
    }
    __syncthreads();
    const float invSum = sRed[33];

    // ---- stage 4: weighted pool (4 s-groups x 64 dims, all 256 threads) ------
    {
        const int g = t >> 6, d = t & 63;
        const int s0 = g * 50;
        float acc = 0.0f;
        #pragma unroll 2
        for (int s = s0; s < s0 + 50; s++) {
            uint32_t off = SWZ((uint32_t)(s * 128 + d * 2));
            float xh = __half2float(*(__half*)(smemc + SB_XH + off));
            float xl = __half2float(*(__half*)(smemc + SB_XL + off));
            acc += sLg[s] * (xh + xl);
        }
        sPool[t] = acc;
    }
    __syncthreads();

    // ---- stage 5: BN + concat epilogue ----------------------------------------
    float* ob = out + (size_t)b * 192;
    if (t < 192) {
        int i = t;
        if (i < 128) {
            float v = (i < 64)
                ? (sPool[i] + sPool[64 + i] + sPool[128 + i] + sPool[192 + i]) * invSum
                : sQ[i - 64];
            ob[i] = (v - mmean[i]) * rsqrtf(mvar[i] + 1e-3f) * gamma[i] + beta[i];
        } else {
            ob[i] = eu[(size_t)b * 64 + (i - 128)];
        }
    }
}

extern "C" void kernel_launch(void* const* d_in, const int* in_sizes, int n_in,
                              void* d_out, int out_size)
{
    const float* em    = (const float*)d_in[0];
    const float* eu    = (const float*)d_in[1];
    const float* Xu    = (const float*)d_in[2];
    const float* W1    = (const float*)d_in[3];
    const float* b1    = (const float*)d_in[4];
    const float* W2    = (const float*)d_in[5];
    const float* b2    = (const float*)d_in[6];
    const float* W3    = (const float*)d_in[7];
    const float* b3    = (const float*)d_in[8];
    const float* gamma = (const float*)d_in[9];
    const float* beta  = (const float*)d_in[10];
    const float* mmean = (const float*)d_in[11];
    const float* mvar  = (const float*)d_in[12];
    float* out = (float*)d_out;

    const int B = in_sizes[0] / 64;

    cudaFuncSetAttribute(din_user_repr_kernel,
                         cudaFuncAttributeMaxDynamicSharedMemorySize, SMEM_BYTES);
    din_user_repr_kernel<<<B, TPB, SMEM_BYTES>>>(
        em, eu, Xu, W1, b1, W2, b2, W3, b3, gamma, beta, mmean, mvar, out);
}

// round 14
// speedup vs baseline: 4.4913x; 1.5997x over previous
#include <cuda_runtime.h>
#include <cuda_fp16.h>
#include <cstdint>

#define TPB    256
#define S_LEN  200

// ---- smem layout (bytes). fp16 tiles: 128B rows, SW128 swizzle ----
#define SB_XH   0            // X hi : 208 rows x 128B (fp16[208][64])
#define SB_XL   26624        // X lo
#define SB_MH   53248        // M^T hi: 64 rows x 128B (fp16[64][64])
#define SB_ML   61440        // M^T lo
#define SB_WH   69632        // W2^T hi: 32 rows x 128B (fp16[32][64])
#define SB_WL   73728        // W2^T lo
#define SB_F    77824        // float region
#define SMEM_BYTES (SB_F + 3072)   // 80896 B -> 2 CTAs/SM

// float-region offsets (floats)
#define F_C0    0     // 64
#define F_Q     64    // 64
#define F_B2    128   // 32
#define F_W3    160   // 32
#define F_LG    192   // 208
#define F_RED   400   // 48
#define F_POOL  448   // 256 (4 groups x 64; also c0-partial scratch)

#define SWZ(o) ((o) ^ (((o) >> 3) & 0x70))

// ---------------- helpers ----------------
__device__ __forceinline__ uint32_t smem_u32(const void* p) {
    uint32_t a;
    asm("{ .reg .u64 t; cvta.to.shared.u64 t, %1; cvt.u32.u64 %0, t; }" : "=r"(a) : "l"(p));
    return a;
}
__device__ __forceinline__ void ldsm4(uint32_t& r0, uint32_t& r1, uint32_t& r2, uint32_t& r3,
                                      uint32_t addr) {
    asm volatile("ldmatrix.sync.aligned.m8n8.x4.shared.b16 {%0,%1,%2,%3}, [%4];"
                 : "=r"(r0), "=r"(r1), "=r"(r2), "=r"(r3) : "r"(addr));
}
__device__ __forceinline__ void mma16816(float& d0, float& d1, float& d2, float& d3,
                                         uint32_t a0, uint32_t a1, uint32_t a2, uint32_t a3,
                                         uint32_t b0, uint32_t b1) {
    asm volatile("mma.sync.aligned.m16n8k16.row.col.f32.f16.f16.f32 "
                 "{%0,%1,%2,%3}, {%4,%5,%6,%7}, {%8,%9}, {%0,%1,%2,%3};"
                 : "+f"(d0), "+f"(d1), "+f"(d2), "+f"(d3)
                 : "r"(a0), "r"(a1), "r"(a2), "r"(a3), "r"(b0), "r"(b1));
}
__device__ __forceinline__ uint32_t packh(__half a, __half b) {
    __half2 h = __halves2half2(a, b);
    return *reinterpret_cast<uint32_t*>(&h);
}
__device__ __forceinline__ void split2(float v0, float v1, uint32_t& hi, uint32_t& lo) {
    __half h0 = __float2half_rn(v0), h1 = __float2half_rn(v1);
    float r0 = v0 - __half2float(h0), r1 = v1 - __half2float(h1);
    hi = packh(h0, h1);
    lo = packh(__float2half_rn(r0), __float2half_rn(r1));
}

// ---------------- kernel ----------------
__global__ void __launch_bounds__(TPB, 2)
din_user_repr_kernel(const float* __restrict__ em,
                     const float* __restrict__ eu,
                     const float* __restrict__ Xu,
                     const float* __restrict__ W1,
                     const float* __restrict__ b1,
                     const float* __restrict__ W2,
                     const float* __restrict__ b2,
                     const float* __restrict__ W3,
                     const float* __restrict__ b3,
                     const float* __restrict__ gamma,
                     const float* __restrict__ beta,
                     const float* __restrict__ mmean,
                     const float* __restrict__ mvar,
                     float* __restrict__ out)
{
    extern __shared__ char smemc[];
    float* sF   = (float*)(smemc + SB_F);
    float* sC0  = sF + F_C0;
    float* sQ   = sF + F_Q;
    float* sB2  = sF + F_B2;
    float* sW3  = sF + F_W3;
    float* sLg  = sF + F_LG;
    float* sRed = sF + F_RED;
    float* sPool= sF + F_POOL;

    const int b   = blockIdx.x;
    const int t   = threadIdx.x;
    const int wid = t >> 5;
    const int lid = t & 31;
    const uint32_t sbase = smem_u32(smemc);
    float* ob = out + (size_t)b * 192;

    // ================= fused barrier-free prologue =================
    // independent epilogue pieces first (latency hidden under everything else)
    if (t < 64) {
        float q = em[(size_t)b * 64 + t];
        sQ[t] = q;
        int i = 64 + t;       // BN over em half of info_all
        ob[i] = (q - mmean[i]) * rsqrtf(mvar[i] + 1e-3f) * gamma[i] + beta[i];
    } else if (t < 96)  sB2[t - 64] = b2[t - 64];
    else if (t < 128)   sW3[t - 96] = W3[t - 96];
    else if (t < 192)   ob[t] = eu[(size_t)b * 64 + (t - 128)];   // eu concat

    {   // X -> (Xh, Xl) fp16, SW128-swizzled 128B rows (float4 loads)
        const float4* Xg4 = (const float4*)(Xu + (size_t)b * S_LEN * 64);
        #pragma unroll 4
        for (int i = t; i < S_LEN * 16; i += TPB) {
            float4 v = Xg4[i];
            int row = i >> 4, p = i & 15;
            uint32_t h0, l0, h1, l1;
            split2(v.x, v.y, h0, l0);
            split2(v.z, v.w, h1, l1);
            uint32_t off = SWZ((uint32_t)(row * 128 + p * 8));
            *(uint2*)(smemc + SB_XH + off) = make_uint2(h0, h1);
            *(uint2*)(smemc + SB_XL + off) = make_uint2(l0, l1);
        }
        // zero pad rows 200..207 (both tiles)
        #pragma unroll
        for (int i = t; i < 512; i += TPB) {
            int tile = i >> 8, j = i & 255;
            int row = 200 + (j >> 5), p = j & 31;
            uint32_t off = SWZ((uint32_t)(row * 128 + p * 4));
            *(uint32_t*)(smemc + (tile ? SB_XL : SB_XH) + off) = 0;
        }
    }
    {   // W2^T -> hi/lo (W2T[n][k] = W2[k][n])
        #pragma unroll 4
        for (int i = t; i < 64 * 32; i += TPB) {
            int k = i >> 5, n = i & 31;
            float w = W2[k * 32 + n];
            __half wh = __float2half_rn(w);
            __half wl = __float2half_rn(w - __half2float(wh));
            uint32_t off = SWZ((uint32_t)(n * 128 + k * 2));
            *(__half*)(smemc + SB_WH + off) = wh;
            *(__half*)(smemc + SB_WL + off) = wl;
        }
    }
    // merged W1-fold + c0 partials; q via broadcast __ldg (no barrier needed)
    {
        const int j = t & 63;
        float cacc = 0.0f;
        #pragma unroll 4
        for (int k = 0; k < 16; k++) {
            int d = (t >> 6) + 4 * k;
            float q  = __ldg(em + (size_t)b * 64 + d);          // broadcast per 64-thread group
            float wa = W1[d * 64 + j];
            float wb = W1[(64 + d) * 64 + j];
            float wc = W1[(128 + d) * 64 + j];
            float wd = W1[(192 + d) * 64 + j];
            float m  = wb - wc + q * wd;
            cacc += q * (wa + wc);
            __half mh = __float2half_rn(m);
            __half ml = __float2half_rn(m - __half2float(mh));
            uint32_t off = SWZ((uint32_t)(j * 128 + d * 2));    // M^T[j][d]
            *(__half*)(smemc + SB_MH + off) = mh;
            *(__half*)(smemc + SB_ML + off) = ml;
        }
        sPool[t] = cacc;   // 4 partials per j (threads t, t+64, t+128, t+192)
    }
    __syncthreads();                                            // B1: smem tiles + partials
    if (t < 64)
        sC0[t] = b1[t] + sPool[t] + sPool[t + 64] + sPool[t + 128] + sPool[t + 192];
    __syncthreads();                                            // B2: sC0

    // ================= tensor-core MLP, 13 m-tiles over 8 warps =================
    {
        const int i8  = lid & 7;
        const int sel = lid >> 3;
        const int tig = lid & 3;
        const int gid = lid >> 2;
        const float bb3 = __ldg(b3);

        for (int mt = wid; mt < 13; mt += 8) {
            const int m0 = mt * 16;

            // --- A frags for X hi/lo (4 k-chunks) ---
            uint32_t Ah[4][4], Al[4][4];
            #pragma unroll
            for (int kc = 0; kc < 4; kc++) {
                uint32_t off = SWZ((uint32_t)((m0 + ((sel & 1) << 3) + i8) * 128
                                              + kc * 32 + ((sel & 2) << 3)));
                ldsm4(Ah[kc][0], Ah[kc][1], Ah[kc][2], Ah[kc][3], sbase + SB_XH + off);
                ldsm4(Al[kc][0], Al[kc][1], Al[kc][2], Al[kc][3], sbase + SB_XL + off);
            }

            // --- layer 1: C1[8 n-tiles] = Xh@Mh + Xh@Ml + Xl@Mh ---
            float c1[8][4];
            #pragma unroll
            for (int nt = 0; nt < 8; nt++) {
                c1[nt][0] = 0.f; c1[nt][1] = 0.f; c1[nt][2] = 0.f; c1[nt][3] = 0.f;
            }
            #pragma unroll
            for (int kc = 0; kc < 4; kc++) {
                uint32_t Bh[4][4], Bl[4][4];
                #pragma unroll
                for (int q = 0; q < 4; q++) {
                    uint32_t off = SWZ((uint32_t)((16 * q + ((sel >> 1) << 3) + i8) * 128
                                                  + kc * 32 + ((sel & 1) << 4)));
                    ldsm4(Bh[q][0], Bh[q][1], Bh[q][2], Bh[q][3], sbase + SB_MH + off);
                    ldsm4(Bl[q][0], Bl[q][1], Bl[q][2], Bl[q][3], sbase + SB_ML + off);
                }
                #pragma unroll
                for (int nt = 0; nt < 8; nt++) {
                    uint32_t bh0 = Bh[nt >> 1][(nt & 1) * 2], bh1 = Bh[nt >> 1][(nt & 1) * 2 + 1];
                    uint32_t bl0 = Bl[nt >> 1][(nt & 1) * 2], bl1 = Bl[nt >> 1][(nt & 1) * 2 + 1];
                    mma16816(c1[nt][0], c1[nt][1], c1[nt][2], c1[nt][3],
                             Ah[kc][0], Ah[kc][1], Ah[kc][2], Ah[kc][3], bh0, bh1);
                    mma16816(c1[nt][0], c1[nt][1], c1[nt][2], c1[nt][3],
                             Ah[kc][0], Ah[kc][1], Ah[kc][2], Ah[kc][3], bl0, bl1);
                    mma16816(c1[nt][0], c1[nt][1], c1[nt][2], c1[nt][3],
                             Al[kc][0], Al[kc][1], Al[kc][2], Al[kc][3], bh0, bh1);
                }
            }

            // --- epilogue 1: +c0, relu, split -> layer-2 A frags (registers) ---
            uint32_t A2h[4][4], A2l[4][4];
            #pragma unroll
            for (int nt = 0; nt < 8; nt++) {
                float2 c0p = *(const float2*)&sC0[8 * nt + 2 * tig];
                float v0 = fmaxf(c1[nt][0] + c0p.x, 0.f);
                float v1 = fmaxf(c1[nt][1] + c0p.y, 0.f);
                float v2 = fmaxf(c1[nt][2] + c0p.x, 0.f);
                float v3 = fmaxf(c1[nt][3] + c0p.y, 0.f);
                int kc2 = nt >> 1, r = (nt & 1) * 2;
                split2(v0, v1, A2h[kc2][r],     A2l[kc2][r]);
                split2(v2, v3, A2h[kc2][r + 1], A2l[kc2][r + 1]);
            }

            // --- layer 2: C2[4 n-tiles] = A2h@W2h + A2h@W2l + A2l@W2h ---
            float c2[4][4];
            #pragma unroll
            for (int nt = 0; nt < 4; nt++) {
                c2[nt][0] = 0.f; c2[nt][1] = 0.f; c2[nt][2] = 0.f; c2[nt][3] = 0.f;
            }
            #pragma unroll
            for (int kc = 0; kc < 4; kc++) {
                uint32_t Wh[2][4], Wl[2][4];
                #pragma unroll
                for (int q = 0; q < 2; q++) {
                    uint32_t off = SWZ((uint32_t)((16 * q + ((sel >> 1) << 3) + i8) * 128
                                                  + kc * 32 + ((sel & 1) << 4)));
                    ldsm4(Wh[q][0], Wh[q][1], Wh[q][2], Wh[q][3], sbase + SB_WH + off);
                    ldsm4(Wl[q][0], Wl[q][1], Wl[q][2], Wl[q][3], sbase + SB_WL + off);
                }
                #pragma unroll
                for (int nt = 0; nt < 4; nt++) {
                    uint32_t bh0 = Wh[nt >> 1][(nt & 1) * 2], bh1 = Wh[nt >> 1][(nt & 1) * 2 + 1];
                    uint32_t bl0 = Wl[nt >> 1][(nt & 1) * 2], bl1 = Wl[nt >> 1][(nt & 1) * 2 + 1];
                    mma16816(c2[nt][0], c2[nt][1], c2[nt][2], c2[nt][3],
                             A2h[kc][0], A2h[kc][1], A2h[kc][2], A2h[kc][3], bh0, bh1);
                    mma16816(c2[nt][0], c2[nt][1], c2[nt][2], c2[nt][3],
                             A2h[kc][0], A2h[kc][1], A2h[kc][2], A2h[kc][3], bl0, bl1);
                    mma16816(c2[nt][0], c2[nt][1], c2[nt][2], c2[nt][3],
                             A2l[kc][0], A2l[kc][1], A2l[kc][2], A2l[kc][3], bh0, bh1);
                }
            }

            // --- epilogue 2: +b2, relu, dot W3 -> logits ---
            float lg0 = 0.f, lg1 = 0.f;
            #pragma unroll
            for (int nt = 0; nt < 4; nt++) {
                int j0 = 8 * nt + 2 * tig;
                float2 b2p = *(const float2*)&sB2[j0];
                float2 w3p = *(const float2*)&sW3[j0];
                lg0 += fmaxf(c2[nt][0] + b2p.x, 0.f) * w3p.x
                     + fmaxf(c2[nt][1] + b2p.y, 0.f) * w3p.y;
                lg1 += fmaxf(c2[nt][2] + b2p.x, 0.f) * w3p.x
                     + fmaxf(c2[nt][3] + b2p.y, 0.f) * w3p.y;
            }
            lg0 += __shfl_xor_sync(0xffffffffu, lg0, 1);
            lg0 += __shfl_xor_sync(0xffffffffu, lg0, 2);
            lg1 += __shfl_xor_sync(0xffffffffu, lg1, 1);
            lg1 += __shfl_xor_sync(0xffffffffu, lg1, 2);
            if (tig == 0) {
                int r0 = m0 + gid, r1 = m0 + gid + 8;
                if (r0 < S_LEN) sLg[r0] = lg0 + bb3;
                if (r1 < S_LEN) sLg[r1] = lg1 + bb3;
            }
        }
    }
    __syncthreads();                                            // B3: logits

    // ================= fused online softmax (one logit per thread) =============
    const float LOW = -1e30f;
    float v = (t < S_LEN) ? sLg[t] : LOW;
    float m = v;
    float s = (t < S_LEN) ? 1.0f : 0.0f;
    #pragma unroll
    for (int o = 16; o > 0; o >>= 1) {
        float m2 = __shfl_xor_sync(0xffffffffu, m, o);
        float s2 = __shfl_xor_sync(0xffffffffu, s, o);
        float nm = fmaxf(m, m2);
        s = s * __expf(m - nm) + s2 * __expf(m2 - nm);
        m = nm;
    }
    if (lid == 0) { sRed[2 * wid] = m; sRed[2 * wid + 1] = s; }
    __syncthreads();                                            // B4: warp partials
    if (t < 8) {
        float mm = sRed[2 * t], ss = sRed[2 * t + 1];
        #pragma unroll
        for (int o = 4; o > 0; o >>= 1) {
            float m2 = __shfl_xor_sync(0xffu, mm, o, 8);
            float s2 = __shfl_xor_sync(0xffu, ss, o, 8);
            float nm = fmaxf(mm, m2);
            ss = ss * __expf(mm - nm) + s2 * __expf(m2 - nm);
            mm = nm;
        }
        if (t == 0) { sRed[32] = mm; sRed[33] = 1.0f / ss; }
    }
    __syncthreads();                                            // B5: M, invS
    const float mx = sRed[32];
    const float invSum = sRed[33];
    if (t < S_LEN) sLg[t] = __expf(v - mx);
    __syncthreads();                                            // B6: exp weights

    // ================= weighted pool (4 s-groups x 64 dims) =====================
    {
        const int g = t >> 6, d = t & 63;
        const int s0 = g * 50;
        float acc0 = 0.0f, acc1 = 0.0f;
        #pragma unroll 5
        for (int s5 = s0; s5 < s0 + 25; s5++) {
            uint32_t offA = SWZ((uint32_t)(s5 * 128 + d * 2));
            uint32_t offB = SWZ((uint32_t)((s5 + 25) * 128 + d * 2));
            float xa = __half2float(*(__half*)(smemc + SB_XH + offA))
                     + __half2float(*(__half*)(smemc + SB_XL + offA));
            float xb = __half2float(*(__half*)(smemc + SB_XH + offB))
                     + __half2float(*(__half*)(smemc + SB_XL + offB));
            acc0 += sLg[s5] * xa;
            acc1 += sLg[s5 + 25] * xb;
        }
        sPool[t] = acc0 + acc1;
    }
    __syncthreads();                                            // B7: pool partials

    // ================= pooled-half BN =================
    if (t < 64) {
        float pv = (sPool[t] + sPool[64 + t] + sPool[128 + t] + sPool[192 + t]) * invSum;
        ob[t] = (pv - mmean[t]) * rsqrtf(mvar[t] + 1e-3f) * gamma[t] + beta[t];
    }
}

extern "C" void kernel_launch(void* const* d_in, const int* in_sizes, int n_in,
                              void* d_out, int out_size)
{
    const float* em    = (const float*)d_in[0];
    const float* eu    = (const float*)d_in[1];
    const float* Xu    = (const float*)d_in[2];
    const float* W1    = (const float*)d_in[3];
    const float* b1    = (const float*)d_in[4];
    const float* W2    = (const float*)d_in[5];
    const float* b2    = (const float*)d_in[6];
    const float* W3    = (const float*)d_in[7];
    const float* b3    = (const float*)d_in[8];
    const float* gamma = (const float*)d_in[9];
    const float* beta  = (const float*)d_in[10];
    const float* mmean = (const float*)d_in[11];
    const float* mvar  = (const float*)d_in[12];
    float* out = (float*)d_out;

    const int B = in_sizes[0] / 64;

    cudaFuncSetAttribute(din_user_repr_kernel,
                         cudaFuncAttributeMaxDynamicSharedMemorySize, SMEM_BYTES);
    din_user_repr_kernel<<<B, TPB, SMEM_BYTES>>>(
        em, eu, Xu, W1, b1, W2, b2, W3, b3, gamma, beta, mmean, mvar, out);
}

// round 15
// speedup vs baseline: 4.8402x; 1.0777x over previous
#include <cuda_runtime.h>
#include <cuda_fp16.h>
#include <cstdint>

#define TPB    256
#define S_LEN  200

// ---- smem layout (bytes). fp16 tiles: 128B rows, SW128 swizzle ----
#define SB_XH   0            // X hi : 208 rows x 128B (fp16[208][64])
#define SB_XL   26624        // X lo
#define SB_MH   53248        // M^T hi: 64 rows x 128B (fp16[64][64])
#define SB_ML   61440        // M^T lo
#define SB_WH   69632        // W2^T hi: 32 rows x 128B (fp16[32][64])
#define SB_WL   73728        // W2^T lo
#define SB_F    77824        // float region
#define SMEM_BYTES (SB_F + 3072)   // 80896 B -> 2 CTAs/SM

// float-region offsets (floats)
#define F_C0    0     // 64
#define F_B2    128   // 32
#define F_W3    160   // 32
#define F_LG    192   // 208
#define F_RED   400   // 48
#define F_POOL  448   // 256 (4 groups x 64; also c0-partial scratch)

#define SWZ(o) ((o) ^ (((o) >> 3) & 0x70))

// ---------------- helpers ----------------
__device__ __forceinline__ uint32_t smem_u32(const void* p) {
    uint32_t a;
    asm("{ .reg .u64 t; cvta.to.shared.u64 t, %1; cvt.u32.u64 %0, t; }" : "=r"(a) : "l"(p));
    return a;
}
__device__ __forceinline__ void ldsm4(uint32_t& r0, uint32_t& r1, uint32_t& r2, uint32_t& r3,
                                      uint32_t addr) {
    asm volatile("ldmatrix.sync.aligned.m8n8.x4.shared.b16 {%0,%1,%2,%3}, [%4];"
                 : "=r"(r0), "=r"(r1), "=r"(r2), "=r"(r3) : "r"(addr));
}
__device__ __forceinline__ void mma16816(float& d0, float& d1, float& d2, float& d3,
                                         uint32_t a0, uint32_t a1, uint32_t a2, uint32_t a3,
                                         uint32_t b0, uint32_t b1) {
    asm volatile("mma.sync.aligned.m16n8k16.row.col.f32.f16.f16.f32 "
                 "{%0,%1,%2,%3}, {%4,%5,%6,%7}, {%8,%9}, {%0,%1,%2,%3};"
                 : "+f"(d0), "+f"(d1), "+f"(d2), "+f"(d3)
                 : "r"(a0), "r"(a1), "r"(a2), "r"(a3), "r"(b0), "r"(b1));
}
__device__ __forceinline__ uint32_t packh(__half a, __half b) {
    __half2 h = __halves2half2(a, b);
    return *reinterpret_cast<uint32_t*>(&h);
}
__device__ __forceinline__ void split2(float v0, float v1, uint32_t& hi, uint32_t& lo) {
    __half h0 = __float2half_rn(v0), h1 = __float2half_rn(v1);
    float r0 = v0 - __half2float(h0), r1 = v1 - __half2float(h1);
    hi = packh(h0, h1);
    lo = packh(__float2half_rn(r0), __float2half_rn(r1));
}

// ---------------- kernel ----------------
__global__ void __launch_bounds__(TPB, 2)
din_user_repr_kernel(const float* __restrict__ em,
                     const float* __restrict__ eu,
                     const float* __restrict__ Xu,
                     const float* __restrict__ W1,
                     const float* __restrict__ b1,
                     const float* __restrict__ W2,
                     const float* __restrict__ b2,
                     const float* __restrict__ W3,
                     const float* __restrict__ b3,
                     const float* __restrict__ gamma,
                     const float* __restrict__ beta,
                     const float* __restrict__ mmean,
                     const float* __restrict__ mvar,
                     float* __restrict__ out)
{
    extern __shared__ char smemc[];
    float* sF   = (float*)(smemc + SB_F);
    float* sC0  = sF + F_C0;
    float* sB2  = sF + F_B2;
    float* sW3  = sF + F_W3;
    float* sLg  = sF + F_LG;
    float* sRed = sF + F_RED;
    float* sPool= sF + F_POOL;

    const int b   = blockIdx.x;
    const int t   = threadIdx.x;
    const int wid = t >> 5;
    const int lid = t & 31;
    const uint32_t sbase = smem_u32(smemc);
    float* ob = out + (size_t)b * 192;

    // ================= fused barrier-free prologue =================
    if (t < 64) {
        float q = em[(size_t)b * 64 + t];
        int i = 64 + t;       // BN over em half of info_all
        ob[i] = (q - mmean[i]) * rsqrtf(mvar[i] + 1e-3f) * gamma[i] + beta[i];
    } else if (t < 96)  sB2[t - 64] = b2[t - 64];
    else if (t < 128)   sW3[t - 96] = W3[t - 96];
    else if (t < 192)   ob[t] = eu[(size_t)b * 64 + (t - 128)];   // eu concat

    {   // X -> (Xh, Xl) fp16, SW128-swizzled 128B rows (float4 loads)
        const float4* Xg4 = (const float4*)(Xu + (size_t)b * S_LEN * 64);
        #pragma unroll 4
        for (int i = t; i < S_LEN * 16; i += TPB) {
            float4 v = Xg4[i];
            int row = i >> 4, p = i & 15;
            uint32_t h0, l0, h1, l1;
            split2(v.x, v.y, h0, l0);
            split2(v.z, v.w, h1, l1);
            uint32_t off = SWZ((uint32_t)(row * 128 + p * 8));
            *(uint2*)(smemc + SB_XH + off) = make_uint2(h0, h1);
            *(uint2*)(smemc + SB_XL + off) = make_uint2(l0, l1);
        }
        // zero pad rows 200..207 (both tiles)
        #pragma unroll
        for (int i = t; i < 512; i += TPB) {
            int tile = i >> 8, j = i & 255;
            int row = 200 + (j >> 5), p = j & 31;
            uint32_t off = SWZ((uint32_t)(row * 128 + p * 4));
            *(uint32_t*)(smemc + (tile ? SB_XL : SB_XH) + off) = 0;
        }
    }
    {   // W2^T -> hi/lo (W2T[n][k] = W2[k][n])
        #pragma unroll 4
        for (int i = t; i < 64 * 32; i += TPB) {
            int k = i >> 5, n = i & 31;
            float w = W2[k * 32 + n];
            __half wh = __float2half_rn(w);
            __half wl = __float2half_rn(w - __half2float(wh));
            uint32_t off = SWZ((uint32_t)(n * 128 + k * 2));
            *(__half*)(smemc + SB_WH + off) = wh;
            *(__half*)(smemc + SB_WL + off) = wl;
        }
    }
    // merged W1-fold + c0 partials; q via broadcast __ldg; packed STS.64 stores
    {
        const int j   = t & 63;
        const int grp = t >> 6;                 // 0..3, d in [grp*16, grp*16+16)
        const float* emb = em + (size_t)b * 64;
        float cacc = 0.0f;
        #pragma unroll
        for (int c = 0; c < 4; c++) {
            int d0 = grp * 16 + c * 4;
            uint32_t hh[2], ll[2];
            #pragma unroll
            for (int p = 0; p < 2; p++) {
                float mv[2];
                #pragma unroll
                for (int e = 0; e < 2; e++) {
                    int d = d0 + p * 2 + e;
                    float q  = __ldg(emb + d);
                    float wa = W1[d * 64 + j];
                    float wb = W1[(64 + d) * 64 + j];
                    float wc = W1[(128 + d) * 64 + j];
                    float wd = W1[(192 + d) * 64 + j];
                    mv[e] = wb - wc + q * wd;
                    cacc += q * (wa + wc);
                }
                __half2 h2 = __floats2half2_rn(mv[0], mv[1]);
                float2 hf  = __half22float2(h2);
                __half2 l2 = __floats2half2_rn(mv[0] - hf.x, mv[1] - hf.y);
                hh[p] = *(uint32_t*)&h2;
                ll[p] = *(uint32_t*)&l2;
            }
            uint32_t off = SWZ((uint32_t)(j * 128 + d0 * 2));   // M^T[j][d0..d0+3]
            *(uint2*)(smemc + SB_MH + off) = make_uint2(hh[0], hh[1]);
            *(uint2*)(smemc + SB_ML + off) = make_uint2(ll[0], ll[1]);
        }
        sPool[t] = cacc;   // 4 partials per j
    }
    __syncthreads();                                            // B1
    if (t < 64)
        sC0[t] = b1[t] + sPool[t] + sPool[t + 64] + sPool[t + 128] + sPool[t + 192];
    __syncthreads();                                            // B2

    // ========== tensor-core MLP: one m32 tile per warp (7 warps) ==========
    if (wid < 7) {
        const int i8  = lid & 7;
        const int sel = lid >> 3;
        const int tig = lid & 3;
        const int gid = lid >> 2;
        const float bb3 = __ldg(b3);
        const int m0 = wid * 32;   // warp 6: rows 192-223; 208-223 are garbage, never stored

        // --- layer 1: C1[2 subs][8 nt] = Xh@Mh + Xh@Ml + Xl@Mh, B loaded once/kc ---
        float c1[2][8][4];
        #pragma unroll
        for (int sub = 0; sub < 2; sub++)
            #pragma unroll
            for (int nt = 0; nt < 8; nt++) {
                c1[sub][nt][0] = 0.f; c1[sub][nt][1] = 0.f;
                c1[sub][nt][2] = 0.f; c1[sub][nt][3] = 0.f;
            }
        #pragma unroll
        for (int kc = 0; kc < 4; kc++) {
            uint32_t Bh[4][4], Bl[4][4];
            #pragma unroll
            for (int q = 0; q < 4; q++) {
                uint32_t off = SWZ((uint32_t)((16 * q + ((sel >> 1) << 3) + i8) * 128
                                              + kc * 32 + ((sel & 1) << 4)));
                ldsm4(Bh[q][0], Bh[q][1], Bh[q][2], Bh[q][3], sbase + SB_MH + off);
                ldsm4(Bl[q][0], Bl[q][1], Bl[q][2], Bl[q][3], sbase + SB_ML + off);
            }
            #pragma unroll
            for (int sub = 0; sub < 2; sub++) {
                uint32_t Ah[4], Al[4];
                uint32_t offA = SWZ((uint32_t)((m0 + sub * 16 + ((sel & 1) << 3) + i8) * 128
                                               + kc * 32 + ((sel & 2) << 3)));
                ldsm4(Ah[0], Ah[1], Ah[2], Ah[3], sbase + SB_XH + offA);
                ldsm4(Al[0], Al[1], Al[2], Al[3], sbase + SB_XL + offA);
                #pragma unroll
                for (int nt = 0; nt < 8; nt++) {
                    uint32_t bh0 = Bh[nt >> 1][(nt & 1) * 2], bh1 = Bh[nt >> 1][(nt & 1) * 2 + 1];
                    uint32_t bl0 = Bl[nt >> 1][(nt & 1) * 2], bl1 = Bl[nt >> 1][(nt & 1) * 2 + 1];
                    mma16816(c1[sub][nt][0], c1[sub][nt][1], c1[sub][nt][2], c1[sub][nt][3],
                             Ah[0], Ah[1], Ah[2], Ah[3], bh0, bh1);
                    mma16816(c1[sub][nt][0], c1[sub][nt][1], c1[sub][nt][2], c1[sub][nt][3],
                             Ah[0], Ah[1], Ah[2], Ah[3], bl0, bl1);
                    mma16816(c1[sub][nt][0], c1[sub][nt][1], c1[sub][nt][2], c1[sub][nt][3],
                             Al[0], Al[1], Al[2], Al[3], bh0, bh1);
                }
            }
        }

        // --- epilogue 1: +c0, relu, split -> layer-2 A frags (registers) ---
        uint32_t A2h[2][4][4], A2l[2][4][4];
        #pragma unroll
        for (int sub = 0; sub < 2; sub++)
            #pragma unroll
            for (int nt = 0; nt < 8; nt++) {
                float2 c0p = *(const float2*)&sC0[8 * nt + 2 * tig];
                float v0 = fmaxf(c1[sub][nt][0] + c0p.x, 0.f);
                float v1 = fmaxf(c1[sub][nt][1] + c0p.y, 0.f);
                float v2 = fmaxf(c1[sub][nt][2] + c0p.x, 0.f);
                float v3 = fmaxf(c1[sub][nt][3] + c0p.y, 0.f);
                int kc2 = nt >> 1, r = (nt & 1) * 2;
                split2(v0, v1, A2h[sub][kc2][r],     A2l[sub][kc2][r]);
                split2(v2, v3, A2h[sub][kc2][r + 1], A2l[sub][kc2][r + 1]);
            }

        // --- layer 2: C2[2 subs][4 nt] = A2h@W2h + A2h@W2l + A2l@W2h ---
        float c2[2][4][4];
        #pragma unroll
        for (int sub = 0; sub < 2; sub++)
            #pragma unroll
            for (int nt = 0; nt < 4; nt++) {
                c2[sub][nt][0] = 0.f; c2[sub][nt][1] = 0.f;
                c2[sub][nt][2] = 0.f; c2[sub][nt][3] = 0.f;
            }
        #pragma unroll
        for (int kc = 0; kc < 4; kc++) {
            uint32_t Wh[2][4], Wl[2][4];
            #pragma unroll
            for (int q = 0; q < 2; q++) {
                uint32_t off = SWZ((uint32_t)((16 * q + ((sel >> 1) << 3) + i8) * 128
                                              + kc * 32 + ((sel & 1) << 4)));
                ldsm4(Wh[q][0], Wh[q][1], Wh[q][2], Wh[q][3], sbase + SB_WH + off);
                ldsm4(Wl[q][0], Wl[q][1], Wl[q][2], Wl[q][3], sbase + SB_WL + off);
            }
            #pragma unroll
            for (int sub = 0; sub < 2; sub++)
                #pragma unroll
                for (int nt = 0; nt < 4; nt++) {
                    uint32_t bh0 = Wh[nt >> 1][(nt & 1) * 2], bh1 = Wh[nt >> 1][(nt & 1) * 2 + 1];
                    uint32_t bl0 = Wl[nt >> 1][(nt & 1) * 2], bl1 = Wl[nt >> 1][(nt & 1) * 2 + 1];
                    mma16816(c2[sub][nt][0], c2[sub][nt][1], c2[sub][nt][2], c2[sub][nt][3],
                             A2h[sub][kc][0], A2h[sub][kc][1], A2h[sub][kc][2], A2h[sub][kc][3], bh0, bh1);
                    mma16816(c2[sub][nt][0], c2[sub][nt][1], c2[sub][nt][2], c2[sub][nt][3],
                             A2h[sub][kc][0], A2h[sub][kc][1], A2h[sub][kc][2], A2h[sub][kc][3], bl0, bl1);
                    mma16816(c2[sub][nt][0], c2[sub][nt][1], c2[sub][nt][2], c2[sub][nt][3],
                             A2l[sub][kc][0], A2l[sub][kc][1], A2l[sub][kc][2], A2l[sub][kc][3], bh0, bh1);
                }
        }

        // --- epilogue 2: +b2, relu, dot W3 -> logits ---
        #pragma unroll
        for (int sub = 0; sub < 2; sub++) {
            float lg0 = 0.f, lg1 = 0.f;
            #pragma unroll
            for (int nt = 0; nt < 4; nt++) {
                int j0 = 8 * nt + 2 * tig;
                float2 b2p = *(const float2*)&sB2[j0];
                float2 w3p = *(const float2*)&sW3[j0];
                lg0 += fmaxf(c2[sub][nt][0] + b2p.x, 0.f) * w3p.x
                     + fmaxf(c2[sub][nt][1] + b2p.y, 0.f) * w3p.y;
                lg1 += fmaxf(c2[sub][nt][2] + b2p.x, 0.f) * w3p.x
                     + fmaxf(c2[sub][nt][3] + b2p.y, 0.f) * w3p.y;
            }
            lg0 += __shfl_xor_sync(0xffffffffu, lg0, 1);
            lg0 += __shfl_xor_sync(0xffffffffu, lg0, 2);
            lg1 += __shfl_xor_sync(0xffffffffu, lg1, 1);
            lg1 += __shfl_xor_sync(0xffffffffu, lg1, 2);
            if (tig == 0) {
                int r0 = m0 + sub * 16 + gid, r1 = r0 + 8;
                if (r0 < S_LEN) sLg[r0] = lg0 + bb3;
                if (r1 < S_LEN) sLg[r1] = lg1 + bb3;
            }
        }
    }
    __syncthreads();                                            // B3: logits

    // ================= fused online softmax (one logit per thread) =============
    const float LOW = -1e30f;
    float v = (t < S_LEN) ? sLg[t] : LOW;
    float m = v;
    float s = (t < S_LEN) ? 1.0f : 0.0f;
    #pragma unroll
    for (int o = 16; o > 0; o >>= 1) {
        float m2 = __shfl_xor_sync(0xffffffffu, m, o);
        float s2 = __shfl_xor_sync(0xffffffffu, s, o);
        float nm = fmaxf(m, m2);
        s = s * __expf(m - nm) + s2 * __expf(m2 - nm);
        m = nm;
    }
    if (lid == 0) { sRed[2 * wid] = m; sRed[2 * wid + 1] = s; }
    __syncthreads();                                            // B4
    if (t < 8) {
        float mm = sRed[2 * t], ss = sRed[2 * t + 1];
        #pragma unroll
        for (int o = 4; o > 0; o >>= 1) {
            float m2 = __shfl_xor_sync(0xffu, mm, o, 8);
            float s2 = __shfl_xor_sync(0xffu, ss, o, 8);
            float nm = fmaxf(mm, m2);
            ss = ss * __expf(mm - nm) + s2 * __expf(m2 - nm);
            mm = nm;
        }
        if (t == 0) { sRed[32] = mm; sRed[33] = 1.0f / ss; }
    }
    __syncthreads();                                            // B5
    const float mx = sRed[32];
    const float invSum = sRed[33];
    if (t < S_LEN) sLg[t] = __expf(v - mx);
    __syncthreads();                                            // B6

    // ================= weighted pool (4 s-groups x 64 dims) =====================
    {
        const int g = t >> 6, d = t & 63;
        const int s0 = g * 50;
        float acc0 = 0.0f, acc1 = 0.0f;
        #pragma unroll 5
        for (int s5 = s0; s5 < s0 + 25; s5++) {
            uint32_t offA = SWZ((uint32_t)(s5 * 128 + d * 2));
            uint32_t offB = SWZ((uint32_t)((s5 + 25) * 128 + d * 2));
            float xa = __half2float(*(__half*)(smemc + SB_XH + offA))
                     + __half2float(*(__half*)(smemc + SB_XL + offA));
            float xb = __half2float(*(__half*)(smemc + SB_XH + offB))
                     + __half2float(*(__half*)(smemc + SB_XL + offB));
            acc0 += sLg[s5] * xa;
            acc1 += sLg[s5 + 25] * xb;
        }
        sPool[t] = acc0 + acc1;
    }
    __syncthreads();                                            // B7

    // ================= pooled-half BN =================
    if (t < 64) {
        float pv = (sPool[t] + sPool[64 + t] + sPool[128 + t] + sPool[192 + t]) * invSum;
        ob[t] = (pv - mmean[t]) * rsqrtf(mvar[t] + 1e-3f) * gamma[t] + beta[t];
    }
}

extern "C" void kernel_launch(void* const* d_in, const int* in_sizes, int n_in,
                              void* d_out, int out_size)
{
    const float* em    = (const float*)d_in[0];
    const float* eu    = (const float*)d_in[1];
    const float* Xu    = (const float*)d_in[2];
    const float* W1    = (const float*)d_in[3];
    const float* b1    = (const float*)d_in[4];
    const float* W2    = (const float*)d_in[5];
    const float* b2    = (const float*)d_in[6];
    const float* W3    = (const float*)d_in[7];
    const float* b3    = (const float*)d_in[8];
    const float* gamma = (const float*)d_in[9];
    const float* beta  = (const float*)d_in[10];
    const float* mmean = (const float*)d_in[11];
    const float* mvar  = (const float*)d_in[12];
    float* out = (float*)d_out;

    const int B = in_sizes[0] / 64;

    cudaFuncSetAttribute(din_user_repr_kernel,
                         cudaFuncAttributeMaxDynamicSharedMemorySize, SMEM_BYTES);
    din_user_repr_kernel<<<B, TPB, SMEM_BYTES>>>(
        em, eu, Xu, W1, b1, W2, b2, W3, b3, gamma, beta, mmean, mvar, out);
}

// round 16
// speedup vs baseline: 6.6780x; 1.3797x over previous
#include <cuda_runtime.h>
#include <cuda_fp16.h>
#include <cstdint>

#define TPB    256
#define S_LEN  200

// ---- smem layout (bytes). fp16 tiles: 128B rows, SW128 swizzle ----
#define SB_XH   0            // X : 208 rows x 128B (fp16[208][64])
#define SB_MH   26624        // M^T: 64 rows x 128B (fp16[64][64])
#define SB_WH   34816        // W2^T: 32 rows x 128B (fp16[32][64])
#define SB_F    38912        // float region
#define SMEM_BYTES (SB_F + 3072)   // 41984 B

// float-region offsets (floats)
#define F_C0    0     // 64
#define F_B2    128   // 32
#define F_W3    160   // 32
#define F_LG    192   // 208
#define F_RED   400   // 48
#define F_POOL  448   // 256 (4 groups x 64; also c0-partial scratch)

#define SWZ(o) ((o) ^ (((o) >> 3) & 0x70))

// ---------------- helpers ----------------
__device__ __forceinline__ uint32_t smem_u32(const void* p) {
    uint32_t a;
    asm("{ .reg .u64 t; cvta.to.shared.u64 t, %1; cvt.u32.u64 %0, t; }" : "=r"(a) : "l"(p));
    return a;
}
__device__ __forceinline__ void ldsm4(uint32_t& r0, uint32_t& r1, uint32_t& r2, uint32_t& r3,
                                      uint32_t addr) {
    asm volatile("ldmatrix.sync.aligned.m8n8.x4.shared.b16 {%0,%1,%2,%3}, [%4];"
                 : "=r"(r0), "=r"(r1), "=r"(r2), "=r"(r3) : "r"(addr));
}
__device__ __forceinline__ void mma16816(float& d0, float& d1, float& d2, float& d3,
                                         uint32_t a0, uint32_t a1, uint32_t a2, uint32_t a3,
                                         uint32_t b0, uint32_t b1) {
    asm volatile("mma.sync.aligned.m16n8k16.row.col.f32.f16.f16.f32 "
                 "{%0,%1,%2,%3}, {%4,%5,%6,%7}, {%8,%9}, {%0,%1,%2,%3};"
                 : "+f"(d0), "+f"(d1), "+f"(d2), "+f"(d3)
                 : "r"(a0), "r"(a1), "r"(a2), "r"(a3), "r"(b0), "r"(b1));
}
__device__ __forceinline__ uint32_t packf2(float a, float b) {
    __half2 h = __floats2half2_rn(a, b);
    return *reinterpret_cast<uint32_t*>(&h);
}

// ---------------- kernel ----------------
__global__ void __launch_bounds__(TPB, 2)
din_user_repr_kernel(const float* __restrict__ em,
                     const float* __restrict__ eu,
                     const float* __restrict__ Xu,
                     const float* __restrict__ W1,
                     const float* __restrict__ b1,
                     const float* __restrict__ W2,
                     const float* __restrict__ b2,
                     const float* __restrict__ W3,
                     const float* __restrict__ b3,
                     const float* __restrict__ gamma,
                     const float* __restrict__ beta,
                     const float* __restrict__ mmean,
                     const float* __restrict__ mvar,
                     float* __restrict__ out)
{
    extern __shared__ char smemc[];
    float* sF   = (float*)(smemc + SB_F);
    float* sC0  = sF + F_C0;
    float* sB2  = sF + F_B2;
    float* sW3  = sF + F_W3;
    float* sLg  = sF + F_LG;
    float* sRed = sF + F_RED;
    float* sPool= sF + F_POOL;

    const int b   = blockIdx.x;
    const int t   = threadIdx.x;
    const int wid = t >> 5;
    const int lid = t & 31;
    const uint32_t sbase = smem_u32(smemc);
    float* ob = out + (size_t)b * 192;

    // ================= fused barrier-free prologue =================
    if (t < 64) {
        float q = em[(size_t)b * 64 + t];
        int i = 64 + t;       // BN over em half of info_all
        ob[i] = (q - mmean[i]) * rsqrtf(mvar[i] + 1e-3f) * gamma[i] + beta[i];
    } else if (t < 96)  sB2[t - 64] = b2[t - 64];
    else if (t < 128)   sW3[t - 96] = W3[t - 96];
    else if (t < 192)   ob[t] = eu[(size_t)b * 64 + (t - 128)];   // eu concat

    {   // X -> fp16, SW128-swizzled 128B rows (float4 loads)
        const float4* Xg4 = (const float4*)(Xu + (size_t)b * S_LEN * 64);
        #pragma unroll 4
        for (int i = t; i < S_LEN * 16; i += TPB) {
            float4 v = Xg4[i];
            int row = i >> 4, p = i & 15;
            uint32_t h01 = packf2(v.x, v.y);
            uint32_t h23 = packf2(v.z, v.w);
            uint32_t off = SWZ((uint32_t)(row * 128 + p * 8));
            *(uint2*)(smemc + SB_XH + off) = make_uint2(h01, h23);
        }
        // zero pad rows 200..207
        #pragma unroll
        for (int i = t; i < 256; i += TPB) {
            int row = 200 + (i >> 5), p = i & 31;
            uint32_t off = SWZ((uint32_t)(row * 128 + p * 4));
            *(uint32_t*)(smemc + SB_XH + off) = 0;
        }
    }
    {   // W2^T -> fp16 (W2T[n][k] = W2[k][n])
        #pragma unroll 4
        for (int i = t; i < 64 * 32; i += TPB) {
            int k = i >> 5, n = i & 31;
            uint32_t off = SWZ((uint32_t)(n * 128 + k * 2));
            *(__half*)(smemc + SB_WH + off) = __float2half_rn(W2[k * 32 + n]);
        }
    }
    // merged W1-fold + c0 partials; q via broadcast __ldg; packed STS.64 stores
    {
        const int j   = t & 63;
        const int grp = t >> 6;                 // 0..3, d in [grp*16, grp*16+16)
        const float* emb = em + (size_t)b * 64;
        float cacc = 0.0f;
        #pragma unroll
        for (int c = 0; c < 4; c++) {
            int d0 = grp * 16 + c * 4;
            float mv[4];
            #pragma unroll
            for (int e = 0; e < 4; e++) {
                int d = d0 + e;
                float q  = __ldg(emb + d);
                float wa = W1[d * 64 + j];
                float wb = W1[(64 + d) * 64 + j];
                float wc = W1[(128 + d) * 64 + j];
                float wd = W1[(192 + d) * 64 + j];
                mv[e] = wb - wc + q * wd;
                cacc += q * (wa + wc);
            }
            uint32_t off = SWZ((uint32_t)(j * 128 + d0 * 2));   // M^T[j][d0..d0+3]
            *(uint2*)(smemc + SB_MH + off) =
                make_uint2(packf2(mv[0], mv[1]), packf2(mv[2], mv[3]));
        }
        sPool[t] = cacc;   // 4 partials per j
    }
    __syncthreads();                                            // B1
    if (t < 64)
        sC0[t] = b1[t] + sPool[t] + sPool[t + 64] + sPool[t + 128] + sPool[t + 192];
    __syncthreads();                                            // B2

    // ========== tensor-core MLP: one m32 tile per warp (7 warps), pure fp16 ====
    if (wid < 7) {
        const int i8  = lid & 7;
        const int sel = lid >> 3;
        const int tig = lid & 3;
        const int gid = lid >> 2;
        const float bb3 = __ldg(b3);
        const int m0 = wid * 32;   // warp 6 rows >=200 are garbage, never stored

        // --- layer 1: C1[2 subs][8 nt] = X@M, B loaded once per kc ---
        float c1[2][8][4];
        #pragma unroll
        for (int sub = 0; sub < 2; sub++)
            #pragma unroll
            for (int nt = 0; nt < 8; nt++) {
                c1[sub][nt][0] = 0.f; c1[sub][nt][1] = 0.f;
                c1[sub][nt][2] = 0.f; c1[sub][nt][3] = 0.f;
            }
        #pragma unroll
        for (int kc = 0; kc < 4; kc++) {
            uint32_t Bh[4][4];
            #pragma unroll
            for (int q = 0; q < 4; q++) {
                uint32_t off = SWZ((uint32_t)((16 * q + ((sel >> 1) << 3) + i8) * 128
                                              + kc * 32 + ((sel & 1) << 4)));
                ldsm4(Bh[q][0], Bh[q][1], Bh[q][2], Bh[q][3], sbase + SB_MH + off);
            }
            #pragma unroll
            for (int sub = 0; sub < 2; sub++) {
                uint32_t Ah[4];
                uint32_t offA = SWZ((uint32_t)((m0 + sub * 16 + ((sel & 1) << 3) + i8) * 128
                                               + kc * 32 + ((sel & 2) << 3)));
                ldsm4(Ah[0], Ah[1], Ah[2], Ah[3], sbase + SB_XH + offA);
                #pragma unroll
                for (int nt = 0; nt < 8; nt++) {
                    mma16816(c1[sub][nt][0], c1[sub][nt][1], c1[sub][nt][2], c1[sub][nt][3],
                             Ah[0], Ah[1], Ah[2], Ah[3],
                             Bh[nt >> 1][(nt & 1) * 2], Bh[nt >> 1][(nt & 1) * 2 + 1]);
                }
            }
        }

        // --- epilogue 1: +c0, relu, pack -> layer-2 A frags (registers) ---
        uint32_t A2h[2][4][4];
        #pragma unroll
        for (int sub = 0; sub < 2; sub++)
            #pragma unroll
            for (int nt = 0; nt < 8; nt++) {
                float2 c0p = *(const float2*)&sC0[8 * nt + 2 * tig];
                float v0 = fmaxf(c1[sub][nt][0] + c0p.x, 0.f);
                float v1 = fmaxf(c1[sub][nt][1] + c0p.y, 0.f);
                float v2 = fmaxf(c1[sub][nt][2] + c0p.x, 0.f);
                float v3 = fmaxf(c1[sub][nt][3] + c0p.y, 0.f);
                int kc2 = nt >> 1, r = (nt & 1) * 2;
                A2h[sub][kc2][r]     = packf2(v0, v1);
                A2h[sub][kc2][r + 1] = packf2(v2, v3);
            }

        // --- layer 2: C2[2 subs][4 nt] = A2@W2 ---
        float c2[2][4][4];
        #pragma unroll
        for (int sub = 0; sub < 2; sub++)
            #pragma unroll
            for (int nt = 0; nt < 4; nt++) {
                c2[sub][nt][0] = 0.f; c2[sub][nt][1] = 0.f;
                c2[sub][nt][2] = 0.f; c2[sub][nt][3] = 0.f;
            }
        #pragma unroll
        for (int kc = 0; kc < 4; kc++) {
            uint32_t Wh[2][4];
            #pragma unroll
            for (int q = 0; q < 2; q++) {
                uint32_t off = SWZ((uint32_t)((16 * q + ((sel >> 1) << 3) + i8) * 128
                                              + kc * 32 + ((sel & 1) << 4)));
                ldsm4(Wh[q][0], Wh[q][1], Wh[q][2], Wh[q][3], sbase + SB_WH + off);
            }
            #pragma unroll
            for (int sub = 0; sub < 2; sub++)
                #pragma unroll
                for (int nt = 0; nt < 4; nt++) {
                    mma16816(c2[sub][nt][0], c2[sub][nt][1], c2[sub][nt][2], c2[sub][nt][3],
                             A2h[sub][kc][0], A2h[sub][kc][1], A2h[sub][kc][2], A2h[sub][kc][3],
                             Wh[nt >> 1][(nt & 1) * 2], Wh[nt >> 1][(nt & 1) * 2 + 1]);
                }
        }

        // --- epilogue 2: +b2, relu, dot W3 -> logits ---
        #pragma unroll
        for (int sub = 0; sub < 2; sub++) {
            float lg0 = 0.f, lg1 = 0.f;
            #pragma unroll
            for (int nt = 0; nt < 4; nt++) {
                int j0 = 8 * nt + 2 * tig;
                float2 b2p = *(const float2*)&sB2[j0];
                float2 w3p = *(const float2*)&sW3[j0];
                lg0 += fmaxf(c2[sub][nt][0] + b2p.x, 0.f) * w3p.x
                     + fmaxf(c2[sub][nt][1] + b2p.y, 0.f) * w3p.y;
                lg1 += fmaxf(c2[sub][nt][2] + b2p.x, 0.f) * w3p.x
                     + fmaxf(c2[sub][nt][3] + b2p.y, 0.f) * w3p.y;
            }
            lg0 += __shfl_xor_sync(0xffffffffu, lg0, 1);
            lg0 += __shfl_xor_sync(0xffffffffu, lg0, 2);
            lg1 += __shfl_xor_sync(0xffffffffu, lg1, 1);
            lg1 += __shfl_xor_sync(0xffffffffu, lg1, 2);
            if (tig == 0) {
                int r0 = m0 + sub * 16 + gid, r1 = r0 + 8;
                if (r0 < S_LEN) sLg[r0] = lg0 + bb3;
                if (r1 < S_LEN) sLg[r1] = lg1 + bb3;
            }
        }
    }
    __syncthreads();                                            // B3: logits

    // ================= fused online softmax (one logit per thread) =============
    const float LOW = -1e30f;
    float v = (t < S_LEN) ? sLg[t] : LOW;
    float m = v;
    float s = (t < S_LEN) ? 1.0f : 0.0f;
    #pragma unroll
    for (int o = 16; o > 0; o >>= 1) {
        float m2 = __shfl_xor_sync(0xffffffffu, m, o);
        float s2 = __shfl_xor_sync(0xffffffffu, s, o);
        float nm = fmaxf(m, m2);
        s = s * __expf(m - nm) + s2 * __expf(m2 - nm);
        m = nm;
    }
    if (lid == 0) { sRed[2 * wid] = m; sRed[2 * wid + 1] = s; }
    __syncthreads();                                            // B4
    if (t < 8) {
        float mm = sRed[2 * t], ss = sRed[2 * t + 1];
        #pragma unroll
        for (int o = 4; o > 0; o >>= 1) {
            float m2 = __shfl_xor_sync(0xffu, mm, o, 8);
            float s2 = __shfl_xor_sync(0xffu, ss, o, 8);
            float nm = fmaxf(mm, m2);
            ss = ss * __expf(mm - nm) + s2 * __expf(m2 - nm);
            mm = nm;
        }
        if (t == 0) { sRed[32] = mm; sRed[33] = 1.0f / ss; }
    }
    __syncthreads();                                            // B5
    const float mx = sRed[32];
    const float invSum = sRed[33];
    if (t < S_LEN) sLg[t] = __expf(v - mx);
    __syncthreads();                                            // B6

    // ================= weighted pool (4 s-groups x 64 dims) =====================
    {
        const int g = t >> 6, d = t & 63;
        const int s0 = g * 50;
        float acc0 = 0.0f, acc1 = 0.0f;
        #pragma unroll 5
        for (int s5 = s0; s5 < s0 + 25; s5++) {
            uint32_t offA = SWZ((uint32_t)(s5 * 128 + d * 2));
            uint32_t offB = SWZ((uint32_t)((s5 + 25) * 128 + d * 2));
            float xa = __half2float(*(__half*)(smemc + SB_XH + offA));
            float xb = __half2float(*(__half*)(smemc + SB_XH + offB));
            acc0 += sLg[s5] * xa;
            acc1 += sLg[s5 + 25] * xb;
        }
        sPool[t] = acc0 + acc1;
    }
    __syncthreads();                                            // B7

    // ================= pooled-half BN =================
    if (t < 64) {
        float pv = (sPool[t] + sPool[64 + t] + sPool[128 + t] + sPool[192 + t]) * invSum;
        ob[t] = (pv - mmean[t]) * rsqrtf(mvar[t] + 1e-3f) * gamma[t] + beta[t];
    }
}

extern "C" void kernel_launch(void* const* d_in, const int* in_sizes, int n_in,
                              void* d_out, int out_size)
{
    const float* em    = (const float*)d_in[0];
    const float* eu    = (const float*)d_in[1];
    const float* Xu    = (const float*)d_in[2];
    const float* W1    = (const float*)d_in[3];
    const float* b1    = (const float*)d_in[4];
    const float* W2    = (const float*)d_in[5];
    const float* b2    = (const float*)d_in[6];
    const float* W3    = (const float*)d_in[7];
    const float* b3    = (const float*)d_in[8];
    const float* gamma = (const float*)d_in[9];
    const float* beta  = (const float*)d_in[10];
    const float* mmean = (const float*)d_in[11];
    const float* mvar  = (const float*)d_in[12];
    float* out = (float*)d_out;

    const int B = in_sizes[0] / 64;

    cudaFuncSetAttribute(din_user_repr_kernel,
                         cudaFuncAttributeMaxDynamicSharedMemorySize, SMEM_BYTES);
    din_user_repr_kernel<<<B, TPB, SMEM_BYTES>>>(
        em, eu, Xu, W1, b1, W2, b2, W3, b3, gamma, beta, mmean, mvar, out);
}

// round 17
// speedup vs baseline: 7.6046x; 1.1388x over previous
#include <cuda_runtime.h>
#include <cuda_fp16.h>
#include <cstdint>

#define TPB    256
#define S_LEN  200

// ---- smem layout (bytes). fp16 tiles: 128B rows, SW128 swizzle ----
#define SB_XH   0            // X : 208 rows x 128B (fp16[208][64])
#define SB_MH   26624        // M^T: 64 rows x 128B (fp16[64][64])
#define SB_WH   34816        // W2^T: 32 rows x 128B (fp16[32][64])
#define SB_F    38912        // float region
#define SMEM_BYTES (SB_F + 3072)   // 41984 B -> 3 CTAs/SM (reg-capped)

// float-region offsets (floats)
#define F_C0    0     // 64
#define F_B2    128   // 32
#define F_W3    160   // 32
#define F_LG    192   // 208
#define F_RED   400   // 48
#define F_POOL  448   // 256 (4 groups x 64; also c0-partial scratch)

#define SWZ(o) ((o) ^ (((o) >> 3) & 0x70))

// ---------------- helpers ----------------
__device__ __forceinline__ uint32_t smem_u32(const void* p) {
    uint32_t a;
    asm("{ .reg .u64 t; cvta.to.shared.u64 t, %1; cvt.u32.u64 %0, t; }" : "=r"(a) : "l"(p));
    return a;
}
__device__ __forceinline__ void ldsm4(uint32_t& r0, uint32_t& r1, uint32_t& r2, uint32_t& r3,
                                      uint32_t addr) {
    asm volatile("ldmatrix.sync.aligned.m8n8.x4.shared.b16 {%0,%1,%2,%3}, [%4];"
                 : "=r"(r0), "=r"(r1), "=r"(r2), "=r"(r3) : "r"(addr));
}
__device__ __forceinline__ void mma16816(float& d0, float& d1, float& d2, float& d3,
                                         uint32_t a0, uint32_t a1, uint32_t a2, uint32_t a3,
                                         uint32_t b0, uint32_t b1) {
    asm volatile("mma.sync.aligned.m16n8k16.row.col.f32.f16.f16.f32 "
                 "{%0,%1,%2,%3}, {%4,%5,%6,%7}, {%8,%9}, {%0,%1,%2,%3};"
                 : "+f"(d0), "+f"(d1), "+f"(d2), "+f"(d3)
                 : "r"(a0), "r"(a1), "r"(a2), "r"(a3), "r"(b0), "r"(b1));
}
__device__ __forceinline__ uint32_t packf2(float a, float b) {
    __half2 h = __floats2half2_rn(a, b);
    return *reinterpret_cast<uint32_t*>(&h);
}

// ---------------- kernel ----------------
__global__ void __launch_bounds__(TPB, 3)
din_user_repr_kernel(const float* __restrict__ em,
                     const float* __restrict__ eu,
                     const float* __restrict__ Xu,
                     const float* __restrict__ W1,
                     const float* __restrict__ b1,
                     const float* __restrict__ W2,
                     const float* __restrict__ b2,
                     const float* __restrict__ W3,
                     const float* __restrict__ b3,
                     const float* __restrict__ gamma,
                     const float* __restrict__ beta,
                     const float* __restrict__ mmean,
                     const float* __restrict__ mvar,
                     float* __restrict__ out)
{
    extern __shared__ char smemc[];
    float* sF   = (float*)(smemc + SB_F);
    float* sC0  = sF + F_C0;
    float* sB2  = sF + F_B2;
    float* sW3  = sF + F_W3;
    float* sLg  = sF + F_LG;
    float* sRed = sF + F_RED;
    float* sPool= sF + F_POOL;

    const int b   = blockIdx.x;
    const int t   = threadIdx.x;
    const int wid = t >> 5;
    const int lid = t & 31;
    const uint32_t sbase = smem_u32(smemc);
    float* ob = out + (size_t)b * 192;

    // ================= fused barrier-free prologue =================
    if (t < 64) {
        float q = em[(size_t)b * 64 + t];
        int i = 64 + t;       // BN over em half of info_all
        ob[i] = (q - mmean[i]) * rsqrtf(mvar[i] + 1e-3f) * gamma[i] + beta[i];
    } else if (t < 96)  sB2[t - 64] = b2[t - 64];
    else if (t < 128)   sW3[t - 96] = W3[t - 96];
    else if (t < 192)   ob[t] = eu[(size_t)b * 64 + (t - 128)];   // eu concat

    {   // X -> fp16, SW128-swizzled 128B rows (float4 loads)
        const float4* Xg4 = (const float4*)(Xu + (size_t)b * S_LEN * 64);
        #pragma unroll 4
        for (int i = t; i < S_LEN * 16; i += TPB) {
            float4 v = Xg4[i];
            int row = i >> 4, p = i & 15;
            uint32_t h01 = packf2(v.x, v.y);
            uint32_t h23 = packf2(v.z, v.w);
            uint32_t off = SWZ((uint32_t)(row * 128 + p * 8));
            *(uint2*)(smemc + SB_XH + off) = make_uint2(h01, h23);
        }
        // zero pad rows 200..207
        #pragma unroll
        for (int i = t; i < 256; i += TPB) {
            int row = 200 + (i >> 5), p = i & 31;
            uint32_t off = SWZ((uint32_t)(row * 128 + p * 4));
            *(uint32_t*)(smemc + SB_XH + off) = 0;
        }
    }
    {   // W2^T -> fp16 (W2T[n][k] = W2[k][n])
        #pragma unroll 4
        for (int i = t; i < 64 * 32; i += TPB) {
            int k = i >> 5, n = i & 31;
            uint32_t off = SWZ((uint32_t)(n * 128 + k * 2));
            *(__half*)(smemc + SB_WH + off) = __float2half_rn(W2[k * 32 + n]);
        }
    }
    // merged W1-fold + c0 partials; q via broadcast __ldg; packed STS.64 stores
    {
        const int j   = t & 63;
        const int grp = t >> 6;                 // 0..3, d in [grp*16, grp*16+16)
        const float* emb = em + (size_t)b * 64;
        float cacc = 0.0f;
        #pragma unroll
        for (int c = 0; c < 4; c++) {
            int d0 = grp * 16 + c * 4;
            float mv[4];
            #pragma unroll
            for (int e = 0; e < 4; e++) {
                int d = d0 + e;
                float q  = __ldg(emb + d);
                float wa = W1[d * 64 + j];
                float wb = W1[(64 + d) * 64 + j];
                float wc = W1[(128 + d) * 64 + j];
                float wd = W1[(192 + d) * 64 + j];
                mv[e] = wb - wc + q * wd;
                cacc += q * (wa + wc);
            }
            uint32_t off = SWZ((uint32_t)(j * 128 + d0 * 2));   // M^T[j][d0..d0+3]
            *(uint2*)(smemc + SB_MH + off) =
                make_uint2(packf2(mv[0], mv[1]), packf2(mv[2], mv[3]));
        }
        sPool[t] = cacc;   // 4 partials per j
    }
    __syncthreads();                                            // B1
    if (t < 64)
        sC0[t] = b1[t] + sPool[t] + sPool[t + 64] + sPool[t + 128] + sPool[t + 192];
    __syncthreads();                                            // B2

    // ==== tensor-core MLP: 13 m16 tiles over 8 warps, low register footprint ====
    {
        const int i8  = lid & 7;
        const int sel = lid >> 3;
        const int tig = lid & 3;
        const int gid = lid >> 2;
        const float bb3 = __ldg(b3);

        for (int mt = wid; mt < 13; mt += 8) {
            const int m0 = mt * 16;
            uint32_t A2h[4][4];           // layer-2 A frags, built across halves

            // --- layer 1 in two n-halves (keeps c1 live set at 16 floats) ---
            #pragma unroll
            for (int h = 0; h < 2; h++) {
                float c1[4][4];
                #pragma unroll
                for (int nt = 0; nt < 4; nt++) {
                    c1[nt][0] = 0.f; c1[nt][1] = 0.f; c1[nt][2] = 0.f; c1[nt][3] = 0.f;
                }
                #pragma unroll
                for (int kc = 0; kc < 4; kc++) {
                    uint32_t Bh[2][4];
                    #pragma unroll
                    for (int q = 0; q < 2; q++) {
                        int qq = 2 * h + q;
                        uint32_t off = SWZ((uint32_t)((16 * qq + ((sel >> 1) << 3) + i8) * 128
                                                      + kc * 32 + ((sel & 1) << 4)));
                        ldsm4(Bh[q][0], Bh[q][1], Bh[q][2], Bh[q][3], sbase + SB_MH + off);
                    }
                    uint32_t Ah[4];
                    uint32_t offA = SWZ((uint32_t)((m0 + ((sel & 1) << 3) + i8) * 128
                                                   + kc * 32 + ((sel & 2) << 3)));
                    ldsm4(Ah[0], Ah[1], Ah[2], Ah[3], sbase + SB_XH + offA);
                    #pragma unroll
                    for (int nt = 0; nt < 4; nt++) {
                        mma16816(c1[nt][0], c1[nt][1], c1[nt][2], c1[nt][3],
                                 Ah[0], Ah[1], Ah[2], Ah[3],
                                 Bh[nt >> 1][(nt & 1) * 2], Bh[nt >> 1][(nt & 1) * 2 + 1]);
                    }
                }
                // epi 1 for this half: +c0, relu, pack -> A2 frags
                #pragma unroll
                for (int nt = 0; nt < 4; nt++) {
                    int gnt = 4 * h + nt;
                    float2 c0p = *(const float2*)&sC0[8 * gnt + 2 * tig];
                    float v0 = fmaxf(c1[nt][0] + c0p.x, 0.f);
                    float v1 = fmaxf(c1[nt][1] + c0p.y, 0.f);
                    float v2 = fmaxf(c1[nt][2] + c0p.x, 0.f);
                    float v3 = fmaxf(c1[nt][3] + c0p.y, 0.f);
                    int kc2 = gnt >> 1, r = (gnt & 1) * 2;
                    A2h[kc2][r]     = packf2(v0, v1);
                    A2h[kc2][r + 1] = packf2(v2, v3);
                }
            }

            // --- layer 2: C2[4 nt] = A2@W2 ---
            float c2[4][4];
            #pragma unroll
            for (int nt = 0; nt < 4; nt++) {
                c2[nt][0] = 0.f; c2[nt][1] = 0.f; c2[nt][2] = 0.f; c2[nt][3] = 0.f;
            }
            #pragma unroll
            for (int kc = 0; kc < 4; kc++) {
                uint32_t Wh[2][4];
                #pragma unroll
                for (int q = 0; q < 2; q++) {
                    uint32_t off = SWZ((uint32_t)((16 * q + ((sel >> 1) << 3) + i8) * 128
                                                  + kc * 32 + ((sel & 1) << 4)));
                    ldsm4(Wh[q][0], Wh[q][1], Wh[q][2], Wh[q][3], sbase + SB_WH + off);
                }
                #pragma unroll
                for (int nt = 0; nt < 4; nt++) {
                    mma16816(c2[nt][0], c2[nt][1], c2[nt][2], c2[nt][3],
                             A2h[kc][0], A2h[kc][1], A2h[kc][2], A2h[kc][3],
                             Wh[nt >> 1][(nt & 1) * 2], Wh[nt >> 1][(nt & 1) * 2 + 1]);
                }
            }

            // --- epilogue 2: +b2, relu, dot W3 -> logits ---
            float lg0 = 0.f, lg1 = 0.f;
            #pragma unroll
            for (int nt = 0; nt < 4; nt++) {
                int j0 = 8 * nt + 2 * tig;
                float2 b2p = *(const float2*)&sB2[j0];
                float2 w3p = *(const float2*)&sW3[j0];
                lg0 += fmaxf(c2[nt][0] + b2p.x, 0.f) * w3p.x
                     + fmaxf(c2[nt][1] + b2p.y, 0.f) * w3p.y;
                lg1 += fmaxf(c2[nt][2] + b2p.x, 0.f) * w3p.x
                     + fmaxf(c2[nt][3] + b2p.y, 0.f) * w3p.y;
            }
            lg0 += __shfl_xor_sync(0xffffffffu, lg0, 1);
            lg0 += __shfl_xor_sync(0xffffffffu, lg0, 2);
            lg1 += __shfl_xor_sync(0xffffffffu, lg1, 1);
            lg1 += __shfl_xor_sync(0xffffffffu, lg1, 2);
            if (tig == 0) {
                int r0 = m0 + gid, r1 = r0 + 8;
                if (r0 < S_LEN) sLg[r0] = lg0 + bb3;
                if (r1 < S_LEN) sLg[r1] = lg1 + bb3;
            }
        }
    }
    __syncthreads();                                            // B3: logits

    // ================= fused online softmax (one logit per thread) =============
    const float LOW = -1e30f;
    float v = (t < S_LEN) ? sLg[t] : LOW;
    float m = v;
    float s = (t < S_LEN) ? 1.0f : 0.0f;
    #pragma unroll
    for (int o = 16; o > 0; o >>= 1) {
        float m2 = __shfl_xor_sync(0xffffffffu, m, o);
        float s2 = __shfl_xor_sync(0xffffffffu, s, o);
        float nm = fmaxf(m, m2);
        s = s * __expf(m - nm) + s2 * __expf(m2 - nm);
        m = nm;
    }
    if (lid == 0) { sRed[2 * wid] = m; sRed[2 * wid + 1] = s; }
    __syncthreads();                                            // B4
    if (t < 8) {
        float mm = sRed[2 * t], ss = sRed[2 * t + 1];
        #pragma unroll
        for (int o = 4; o > 0; o >>= 1) {
            float m2 = __shfl_xor_sync(0xffu, mm, o, 8);
            float s2 = __shfl_xor_sync(0xffu, ss, o, 8);
            float nm = fmaxf(mm, m2);
            ss = ss * __expf(mm - nm) + s2 * __expf(m2 - nm);
            mm = nm;
        }
        if (t == 0) { sRed[32] = mm; sRed[33] = 1.0f / ss; }
    }
    __syncthreads();                                            // B5
    const float mx = sRed[32];
    const float invSum = sRed[33];
    if (t < S_LEN) sLg[t] = __expf(v - mx);
    __syncthreads();                                            // B6

    // ================= weighted pool (4 s-groups x 64 dims) =====================
    {
        const int g = t >> 6, d = t & 63;
        const int s0 = g * 50;
        float acc0 = 0.0f, acc1 = 0.0f;
        #pragma unroll 5
        for (int s5 = s0; s5 < s0 + 25; s5++) {
            uint32_t offA = SWZ((uint32_t)(s5 * 128 + d * 2));
            uint32_t offB = SWZ((uint32_t)((s5 + 25) * 128 + d * 2));
            float xa = __half2float(*(__half*)(smemc + SB_XH + offA));
            float xb = __half2float(*(__half*)(smemc + SB_XH + offB));
            acc0 += sLg[s5] * xa;
            acc1 += sLg[s5 + 25] * xb;
        }
        sPool[t] = acc0 + acc1;
    }
    __syncthreads();                                            // B7

    // ================= pooled-half BN =================
    if (t < 64) {
        float pv = (sPool[t] + sPool[64 + t] + sPool[128 + t] + sPool[192 + t]) * invSum;
        ob[t] = (pv - mmean[t]) * rsqrtf(mvar[t] + 1e-3f) * gamma[t] + beta[t];
    }
}

extern "C" void kernel_launch(void* const* d_in, const int* in_sizes, int n_in,
                              void* d_out, int out_size)
{
    const float* em    = (const float*)d_in[0];
    const float* eu    = (const float*)d_in[1];
    const float* Xu    = (const float*)d_in[2];
    const float* W1    = (const float*)d_in[3];
    const float* b1    = (const float*)d_in[4];
    const float* W2    = (const float*)d_in[5];
    const float* b2    = (const float*)d_in[6];
    const float* W3    = (const float*)d_in[7];
    const float* b3    = (const float*)d_in[8];
    const float* gamma = (const float*)d_in[9];
    const float* beta  = (const float*)d_in[10];
    const float* mmean = (const float*)d_in[11];
    const float* mvar  = (const float*)d_in[12];
    float* out = (float*)d_out;

    const int B = in_sizes[0] / 64;

    cudaFuncSetAttribute(din_user_repr_kernel,
                         cudaFuncAttributeMaxDynamicSharedMemorySize, SMEM_BYTES);
    din_user_repr_kernel<<<B, TPB, SMEM_BYTES>>>(
        em, eu, Xu, W1, b1, W2, b2, W3, b3, gamma, beta, mmean, mvar, out);
}